// round 1
// baseline (speedup 1.0000x reference)
#include <cuda_runtime.h>
#include <math.h>

#define N_NODES 50000
#define N_EDGES 640000
#define D 128
#define H 8

// ---------------- scratch (static device globals; no allocation) ----------------
__device__ float g_Q [N_NODES * D];
__device__ float g_Kf[N_NODES * D];
__device__ float g_Vf[N_NODES * D];
__device__ float g_wV[N_NODES * D];
__device__ float g_z [N_NODES * H];
__device__ float g_x1[N_NODES * D];
__device__ float g_mid[N_NODES * 2 * D];
__device__ float g_x2[N_NODES * D];
__device__ float g_stats[4 * D];   // sum1, sq1, sum2, sq2
__device__ float g_bn1[2 * D];     // scale, shift
__device__ float g_bn2[2 * D];

// ---------------- packed f32x2 helpers (Blackwell FFMA2) ----------------
__device__ __forceinline__ unsigned long long fma2(unsigned long long a,
                                                   unsigned long long b,
                                                   unsigned long long c) {
    unsigned long long d;
    asm("fma.rn.f32x2 %0, %1, %2, %3;" : "=l"(d) : "l"(a), "l"(b), "l"(c));
    return d;
}
__device__ __forceinline__ unsigned long long dup2(float a) {
    unsigned long long d;
    asm("mov.b64 %0, {%1, %1};" : "=l"(d) : "f"(a));
    return d;
}
__device__ __forceinline__ void unpack2(unsigned long long v, float& x, float& y) {
    asm("mov.b64 {%0, %1}, %2;" : "=f"(x), "=f"(y) : "l"(v));
}

// ---------------- zero scratch that must be re-zeroed per replay ----------------
__global__ void zero_scratch() {
    int tid = blockIdx.x * blockDim.x + threadIdx.x;
    int stride = gridDim.x * blockDim.x;
    float4 z4 = make_float4(0.f, 0.f, 0.f, 0.f);
    for (int i = tid; i < N_NODES * D / 4; i += stride) ((float4*)g_wV)[i] = z4;
    for (int i = tid; i < N_NODES * H / 4; i += stride) ((float4*)g_z)[i] = z4;
    if (tid < 4 * D) g_stats[tid] = 0.f;
}

// ---------------- GEMM: C[M,NCOLS] = op(A)[M,K] @ W[NCOLS,K]^T (+epilogue) -------
// 128x128 block tile, BK=16, 256 threads, 8x8 micro-tile per thread, FFMA2 inner.
enum { ATR_NONE = 0, ATR_DIVZ = 1, ATR_BN = 2 };
enum { EPI_STORE = 0, EPI_BIAS_RESID = 1, EPI_BIAS_RELU = 2 };

#define AS 132  // padded shared stride

template <int ATR, int EPI, bool RESBN>
__global__ __launch_bounds__(256) void gemm_k(
    const float* __restrict__ A, const float* __restrict__ W,
    const float* __restrict__ bias, const float* __restrict__ resid,
    const float* __restrict__ t0, const float* __restrict__ t1,
    float* __restrict__ C, int M, int K, int ldc)
{
    __shared__ __align__(16) float sA[16 * AS];
    __shared__ __align__(16) float sB[16 * AS];

    const int tid = threadIdx.x;
    const int tx = tid & 15;
    const int ty = tid >> 4;
    const int rowBase = blockIdx.x * 128;
    const int colBase = blockIdx.y * 128;

    unsigned long long acc[8][4];
#pragma unroll
    for (int r = 0; r < 8; ++r)
#pragma unroll
        for (int c = 0; c < 4; ++c) acc[r][c] = 0ull;

    for (int k0 = 0; k0 < K; k0 += 16) {
#pragma unroll
        for (int it = 0; it < 2; ++it) {
            int idx = tid + it * 256;
            int rl = idx >> 2;
            int kv = idx & 3;
            int kg = k0 + kv * 4;
            // A tile (with optional per-element transform), transposed store
            int row = rowBase + rl;
            float4 av = make_float4(0.f, 0.f, 0.f, 0.f);
            if (row < M) {
                av = *(const float4*)(A + (size_t)row * K + kg);
                if (ATR == ATR_DIVZ) {
                    float iz = 1.0f / t0[row * H + (kg >> 4)];
                    av.x *= iz; av.y *= iz; av.z *= iz; av.w *= iz;
                } else if (ATR == ATR_BN) {
                    float4 sc = *(const float4*)(t0 + kg);
                    float4 sh = *(const float4*)(t1 + kg);
                    av.x = av.x * sc.x + sh.x;
                    av.y = av.y * sc.y + sh.y;
                    av.z = av.z * sc.z + sh.z;
                    av.w = av.w * sc.w + sh.w;
                }
            }
            sA[(kv * 4 + 0) * AS + rl] = av.x;
            sA[(kv * 4 + 1) * AS + rl] = av.y;
            sA[(kv * 4 + 2) * AS + rl] = av.z;
            sA[(kv * 4 + 3) * AS + rl] = av.w;
            // W tile (output col = colBase + rl), transposed store
            float4 wv = *(const float4*)(W + (size_t)(colBase + rl) * K + kg);
            sB[(kv * 4 + 0) * AS + rl] = wv.x;
            sB[(kv * 4 + 1) * AS + rl] = wv.y;
            sB[(kv * 4 + 2) * AS + rl] = wv.z;
            sB[(kv * 4 + 3) * AS + rl] = wv.w;
        }
        __syncthreads();

#pragma unroll
        for (int kk = 0; kk < 16; ++kk) {
            float4 a0 = *(const float4*)(sA + kk * AS + ty * 8);
            float4 a1 = *(const float4*)(sA + kk * AS + ty * 8 + 4);
            ulonglong2 b0 = *(const ulonglong2*)(sB + kk * AS + tx * 8);
            ulonglong2 b1 = *(const ulonglong2*)(sB + kk * AS + tx * 8 + 4);
            unsigned long long br[4] = {b0.x, b0.y, b1.x, b1.y};
            float ar[8] = {a0.x, a0.y, a0.z, a0.w, a1.x, a1.y, a1.z, a1.w};
#pragma unroll
            for (int r = 0; r < 8; ++r) {
                unsigned long long ad = dup2(ar[r]);
#pragma unroll
                for (int c = 0; c < 4; ++c) acc[r][c] = fma2(ad, br[c], acc[r][c]);
            }
        }
        __syncthreads();
    }

    // epilogue
#pragma unroll
    for (int r = 0; r < 8; ++r) {
        int row = rowBase + ty * 8 + r;
        if (row >= M) continue;
#pragma unroll
        for (int c = 0; c < 4; ++c) {
            float v0, v1;
            unpack2(acc[r][c], v0, v1);
            int col = colBase + tx * 8 + c * 2;
            if (EPI == EPI_BIAS_RESID) {
                v0 += bias[col];
                v1 += bias[col + 1];
                float r0 = resid[(size_t)row * D + col];
                float r1 = resid[(size_t)row * D + col + 1];
                if (RESBN) {
                    r0 = r0 * t0[col] + t1[col];
                    r1 = r1 * t0[col + 1] + t1[col + 1];
                }
                v0 += r0;
                v1 += r1;
            } else if (EPI == EPI_BIAS_RELU) {
                v0 = fmaxf(v0 + bias[col], 0.f);
                v1 = fmaxf(v1 + bias[col + 1], 0.f);
            }
            *(float2*)(C + (size_t)row * ldc + col) = make_float2(v0, v1);
        }
    }
}

// ---------------- edge kernel: scores + vectorized scatter ----------------
__global__ void edge_kernel(const float* __restrict__ Q, const float* __restrict__ Km,
                            const float* __restrict__ V,
                            const int* __restrict__ src, const int* __restrict__ dst,
                            float* __restrict__ wV, float* __restrict__ z, int E)
{
    int gid = blockIdx.x * blockDim.x + threadIdx.x;
    if (gid >= E * H) return;
    int e = gid >> 3;
    int hh = gid & 7;
    int s = src[e];
    int d = dst[e];

    const float4* q = (const float4*)(Q + (size_t)d * D + hh * 16);
    const float4* k = (const float4*)(Km + (size_t)s * D + hh * 16);
    float4 q0 = q[0], q1 = q[1], q2 = q[2], q3 = q[3];
    float4 k0 = k[0], k1 = k[1], k2 = k[2], k3 = k[3];
    float dot = q0.x * k0.x + q0.y * k0.y + q0.z * k0.z + q0.w * k0.w
              + q1.x * k1.x + q1.y * k1.y + q1.z * k1.z + q1.w * k1.w
              + q2.x * k2.x + q2.y * k2.y + q2.z * k2.z + q2.w * k2.w
              + q3.x * k3.x + q3.y * k3.y + q3.z * k3.z + q3.w * k3.w;
    float sc = dot * 0.25f;                 // / sqrt(16)
    sc = fminf(fmaxf(sc, -5.f), 5.f);
    sc = expf(sc);

    atomicAdd(z + (size_t)d * H + hh, sc);

    const float4* v = (const float4*)(V + (size_t)s * D + hh * 16);
    float* w = wV + (size_t)d * D + hh * 16;
#pragma unroll
    for (int i = 0; i < 4; ++i) {
        float4 vv = v[i];
        asm volatile("red.global.add.v4.f32 [%0], {%1, %2, %3, %4};"
                     :: "l"(w + i * 4),
                        "f"(vv.x * sc), "f"(vv.y * sc), "f"(vv.z * sc), "f"(vv.w * sc)
                     : "memory");
    }
}

// ---------------- batch-norm stats / finalize / apply ----------------
__global__ void bn_stats(const float* __restrict__ x, float* __restrict__ sum,
                         float* __restrict__ sq, int M)
{
    int col = threadIdx.x & (D - 1);
    int sub = threadIdx.x >> 7;   // 0..1
    float s = 0.f, q = 0.f;
    for (int row = blockIdx.x * 2 + sub; row < M; row += gridDim.x * 2) {
        float v = x[(size_t)row * D + col];
        s += v;
        q += v * v;
    }
    __shared__ float shs[D], shq[D];
    if (sub == 1) { shs[col] = s; shq[col] = q; }
    __syncthreads();
    if (sub == 0) {
        atomicAdd(&sum[col], s + shs[col]);
        atomicAdd(&sq[col], q + shq[col]);
    }
}

__global__ void bn_finalize(const float* __restrict__ sum, const float* __restrict__ sq,
                            const float* __restrict__ g, const float* __restrict__ b,
                            float* __restrict__ scale, float* __restrict__ shift, int M)
{
    int c = threadIdx.x;
    float invM = 1.0f / (float)M;
    float mu = sum[c] * invM;
    float var = sq[c] * invM - mu * mu;
    float sc = g[c] * rsqrtf(var + 1e-5f);
    scale[c] = sc;
    shift[c] = b[c] - mu * sc;
}

__global__ void bn_apply(const float* __restrict__ x, const float* __restrict__ bn,
                         float* __restrict__ out, int M)
{
    int tid = blockIdx.x * blockDim.x + threadIdx.x;
    int stride = gridDim.x * blockDim.x;
    int total = M * D;
    for (int i = tid; i < total; i += stride) {
        int c = i & (D - 1);
        out[i] = x[i] * bn[c] + bn[D + c];
    }
}

// ---------------- host launch ----------------
extern "C" void kernel_launch(void* const* d_in, const int* in_sizes, int n_in,
                              void* d_out, int out_size)
{
    const float* h    = (const float*)d_in[0];
    const int*   src  = (const int*)d_in[1];
    const int*   dst  = (const int*)d_in[2];
    const float* WQ   = (const float*)d_in[3];
    const float* WK   = (const float*)d_in[4];
    const float* WV   = (const float*)d_in[5];
    const float* WO   = (const float*)d_in[6];
    const float* bO   = (const float*)d_in[7];
    const float* W1   = (const float*)d_in[8];
    const float* b1   = (const float*)d_in[9];
    const float* W2   = (const float*)d_in[10];
    const float* b2   = (const float*)d_in[11];
    const float* bn1g = (const float*)d_in[12];
    const float* bn1b = (const float*)d_in[13];
    const float* bn2g = (const float*)d_in[14];
    const float* bn2b = (const float*)d_in[15];
    float* out = (float*)d_out;

    int M = in_sizes[0] / D;
    int E = in_sizes[1];
    if (M > N_NODES) M = N_NODES;
    if (E > N_EDGES) E = N_EDGES;

    float *Qp, *Kp, *Vp, *wVp, *zp, *x1p, *midp, *x2p, *stp, *bn1p, *bn2p;
    cudaGetSymbolAddress((void**)&Qp,  g_Q);
    cudaGetSymbolAddress((void**)&Kp,  g_Kf);
    cudaGetSymbolAddress((void**)&Vp,  g_Vf);
    cudaGetSymbolAddress((void**)&wVp, g_wV);
    cudaGetSymbolAddress((void**)&zp,  g_z);
    cudaGetSymbolAddress((void**)&x1p, g_x1);
    cudaGetSymbolAddress((void**)&midp, g_mid);
    cudaGetSymbolAddress((void**)&x2p, g_x2);
    cudaGetSymbolAddress((void**)&stp, g_stats);
    cudaGetSymbolAddress((void**)&bn1p, g_bn1);
    cudaGetSymbolAddress((void**)&bn2p, g_bn2);

    dim3 blk(256);
    int gx = (M + 127) / 128;

    zero_scratch<<<2048, 256>>>();

    // QKV projections
    gemm_k<ATR_NONE, EPI_STORE, false><<<dim3(gx, 1), blk>>>(
        h, WQ, nullptr, nullptr, nullptr, nullptr, Qp, M, D, D);
    gemm_k<ATR_NONE, EPI_STORE, false><<<dim3(gx, 1), blk>>>(
        h, WK, nullptr, nullptr, nullptr, nullptr, Kp, M, D, D);
    gemm_k<ATR_NONE, EPI_STORE, false><<<dim3(gx, 1), blk>>>(
        h, WV, nullptr, nullptr, nullptr, nullptr, Vp, M, D, D);

    // edge attention scatter
    edge_kernel<<<(E * H + 255) / 256, 256>>>(Qp, Kp, Vp, src, dst, wVp, zp, E);

    // O projection: (wV/z) @ WO^T + bO + h  -> x1
    gemm_k<ATR_DIVZ, EPI_BIAS_RESID, false><<<dim3(gx, 1), blk>>>(
        wVp, WO, bO, h, zp, nullptr, x1p, M, D, D);

    // BN1 stats
    bn_stats<<<512, 256>>>(x1p, stp, stp + D, M);
    bn_finalize<<<1, D>>>(stp, stp + D, bn1g, bn1b, bn1p, bn1p + D, M);

    // FFN1: relu(BN1(x1) @ W1^T + b1) -> mid  [N, 256]
    gemm_k<ATR_BN, EPI_BIAS_RELU, false><<<dim3(gx, 2), blk>>>(
        x1p, W1, b1, nullptr, bn1p, bn1p + D, midp, M, D, 2 * D);

    // FFN2: mid @ W2^T + b2 + BN1(x1) -> x2
    gemm_k<ATR_NONE, EPI_BIAS_RESID, true><<<dim3(gx, 1), blk>>>(
        midp, W2, b2, x1p, bn1p, bn1p + D, x2p, M, 2 * D, D);

    // BN2 stats + apply
    bn_stats<<<512, 256>>>(x2p, stp + 2 * D, stp + 3 * D, M);
    bn_finalize<<<1, D>>>(stp + 2 * D, stp + 3 * D, bn2g, bn2b, bn2p, bn2p + D, M);
    bn_apply<<<2048, 256>>>(x2p, bn2p, out, M);
}

// round 2
// speedup vs baseline: 1.0261x; 1.0261x over previous
#include <cuda_runtime.h>
#include <math.h>

#define N_NODES 50000
#define N_EDGES 640000
#define D 128
#define H 8

// ---------------- scratch (static device globals; no allocation) ----------------
__device__ float g_Q [N_NODES * D];
__device__ float g_Kf[N_NODES * D];
__device__ float g_Vf[N_NODES * D];
__device__ float g_wV[N_NODES * D];
__device__ float g_z [N_NODES * H];
__device__ float g_x1[N_NODES * D];
__device__ float g_mid[N_NODES * 2 * D];
__device__ float g_x2[N_NODES * D];
__device__ float g_stats[4 * D];   // sum1, sq1, sum2, sq2
__device__ float g_bn1[2 * D];     // scale, shift
__device__ float g_bn2[2 * D];

// ---------------- packed f32x2 helpers (Blackwell FFMA2) ----------------
typedef unsigned long long ull;
__device__ __forceinline__ ull fma2(ull a, ull b, ull c) {
    ull d;
    asm("fma.rn.f32x2 %0, %1, %2, %3;" : "=l"(d) : "l"(a), "l"(b), "l"(c));
    return d;
}
__device__ __forceinline__ ull dup2(float a) {
    ull d;
    asm("mov.b64 %0, {%1, %1};" : "=l"(d) : "f"(a));
    return d;
}
__device__ __forceinline__ void unpack2(ull v, float& x, float& y) {
    asm("mov.b64 {%0, %1}, %2;" : "=f"(x), "=f"(y) : "l"(v));
}

// ---------------- zero scratch that must be re-zeroed per replay ----------------
__global__ void zero_scratch() {
    int tid = blockIdx.x * blockDim.x + threadIdx.x;
    int stride = gridDim.x * blockDim.x;
    float4 z4 = make_float4(0.f, 0.f, 0.f, 0.f);
    for (int i = tid; i < N_NODES * D / 4; i += stride) ((float4*)g_wV)[i] = z4;
    for (int i = tid; i < N_NODES * H / 4; i += stride) ((float4*)g_z)[i] = z4;
    if (tid < 4 * D) g_stats[tid] = 0.f;
}

// ---------------- GEMM core: C[M,*] = op(A)[M,K] @ W[*,K]^T (+epilogue) ----------
// 128x128 block tile, BK=16, 256 threads, 8x8 micro-tile, FFMA2, double-buffered.
enum { ATR_NONE = 0, ATR_DIVZ = 1, ATR_BN = 2 };
enum { EPI_STORE = 0, EPI_BIAS_RESID = 1, EPI_BIAS_RELU = 2 };

#define AS 132  // padded shared stride (132*4 = 528 B, 16B-aligned rows)

template <int ATR, int EPI, bool RESBN, int KT>
__device__ __forceinline__ void gemm_core(
    const float* __restrict__ A, const float* __restrict__ W,
    const float* __restrict__ bias, const float* __restrict__ resid,
    const float* __restrict__ t0, const float* __restrict__ t1,
    float* __restrict__ C, int M, int ldc, int rowBase, int colBase)
{
    __shared__ __align__(16) float sA[2][16 * AS];
    __shared__ __align__(16) float sB[2][16 * AS];

    const int tid = threadIdx.x;
    const int tx = tid & 15;
    const int ty = tid >> 4;

    // load-piece geometry: piece p in {0,1}: idx = tid + p*256 ; rl = idx>>2 ; kv = idx&3
    const int rlA[2] = { tid >> 2, (tid + 256) >> 2 };
    const int kvv = tid & 3;

    ull acc[8][4];
#pragma unroll
    for (int r = 0; r < 8; ++r)
#pragma unroll
        for (int c = 0; c < 4; ++c) acc[r][c] = 0ull;

    float4 avR[2], bvR[2];

    // ---- load K-slab k0 into registers ----
    auto LOADG = [&](int k0) {
#pragma unroll
        for (int p = 0; p < 2; ++p) {
            int rl = rlA[p];
            int kg = k0 + kvv * 4;
            int row = rowBase + rl;
            float4 av = make_float4(0.f, 0.f, 0.f, 0.f);
            if (row < M) {
                av = *(const float4*)(A + (size_t)row * KT + kg);
                if (ATR == ATR_DIVZ) {
                    float iz = 1.0f / t0[row * H + (kg >> 4)];
                    av.x *= iz; av.y *= iz; av.z *= iz; av.w *= iz;
                } else if (ATR == ATR_BN) {
                    float4 sc = *(const float4*)(t0 + kg);
                    float4 sh = *(const float4*)(t1 + kg);
                    av.x = av.x * sc.x + sh.x;
                    av.y = av.y * sc.y + sh.y;
                    av.z = av.z * sc.z + sh.z;
                    av.w = av.w * sc.w + sh.w;
                }
            }
            avR[p] = av;
            bvR[p] = *(const float4*)(W + (size_t)(colBase + rl) * KT + kg);
        }
    };
    auto STORES = [&](int buf) {
#pragma unroll
        for (int p = 0; p < 2; ++p) {
            int rl = rlA[p];
            float* a = &sA[buf][(kvv * 4) * AS + rl];
            a[0 * AS] = avR[p].x; a[1 * AS] = avR[p].y;
            a[2 * AS] = avR[p].z; a[3 * AS] = avR[p].w;
            float* b = &sB[buf][(kvv * 4) * AS + rl];
            b[0 * AS] = bvR[p].x; b[1 * AS] = bvR[p].y;
            b[2 * AS] = bvR[p].z; b[3 * AS] = bvR[p].w;
        }
    };

    LOADG(0);
    STORES(0);
    __syncthreads();

    constexpr int NIT = KT / 16;
#pragma unroll
    for (int ki = 0; ki < NIT; ++ki) {
        const int cur = ki & 1;
        if (ki + 1 < NIT) LOADG((ki + 1) * 16);

#pragma unroll
        for (int kk = 0; kk < 16; ++kk) {
            float4 a0 = *(const float4*)(&sA[cur][kk * AS + ty * 8]);
            float4 a1 = *(const float4*)(&sA[cur][kk * AS + ty * 8 + 4]);
            ulonglong2 b0 = *(const ulonglong2*)(&sB[cur][kk * AS + tx * 8]);
            ulonglong2 b1 = *(const ulonglong2*)(&sB[cur][kk * AS + tx * 8 + 4]);
            ull br[4] = {b0.x, b0.y, b1.x, b1.y};
            float ar[8] = {a0.x, a0.y, a0.z, a0.w, a1.x, a1.y, a1.z, a1.w};
#pragma unroll
            for (int r = 0; r < 8; ++r) {
                ull ad = dup2(ar[r]);
#pragma unroll
                for (int c = 0; c < 4; ++c) acc[r][c] = fma2(ad, br[c], acc[r][c]);
            }
        }

        if (ki + 1 < NIT) {
            STORES(cur ^ 1);
            __syncthreads();
        }
    }

    // ---- epilogue ----
#pragma unroll
    for (int r = 0; r < 8; ++r) {
        int row = rowBase + ty * 8 + r;
        if (row >= M) continue;
#pragma unroll
        for (int c = 0; c < 4; ++c) {
            float v0, v1;
            unpack2(acc[r][c], v0, v1);
            int col = colBase + tx * 8 + c * 2;
            if (EPI == EPI_BIAS_RESID) {
                v0 += bias[col];
                v1 += bias[col + 1];
                float r0 = resid[(size_t)row * D + col];
                float r1 = resid[(size_t)row * D + col + 1];
                if (RESBN) {
                    r0 = r0 * t0[col] + t1[col];
                    r1 = r1 * t0[col + 1] + t1[col + 1];
                }
                v0 += r0;
                v1 += r1;
            } else if (EPI == EPI_BIAS_RELU) {
                v0 = fmaxf(v0 + bias[col], 0.f);
                v1 = fmaxf(v1 + bias[col + 1], 0.f);
            }
            *(float2*)(C + (size_t)row * ldc + col) = make_float2(v0, v1);
        }
    }
}

template <int ATR, int EPI, bool RESBN, int KT>
__global__ __launch_bounds__(256, 2) void gemm_k(
    const float* __restrict__ A, const float* __restrict__ W,
    const float* __restrict__ bias, const float* __restrict__ resid,
    const float* __restrict__ t0, const float* __restrict__ t1,
    float* __restrict__ C, int M, int ldc)
{
    gemm_core<ATR, EPI, RESBN, KT>(A, W, bias, resid, t0, t1, C, M, ldc,
                                   blockIdx.x * 128, blockIdx.y * 128);
}

// fused Q/K/V: blockIdx.y selects which projection
__global__ __launch_bounds__(256, 2) void qkv_kernel(
    const float* __restrict__ h,
    const float* __restrict__ WQ, const float* __restrict__ WK, const float* __restrict__ WV,
    float* __restrict__ Q, float* __restrict__ K, float* __restrict__ V, int M)
{
    const float* W = (blockIdx.y == 0) ? WQ : (blockIdx.y == 1) ? WK : WV;
    float* C = (blockIdx.y == 0) ? Q : (blockIdx.y == 1) ? K : V;
    gemm_core<ATR_NONE, EPI_STORE, false, 128>(h, W, nullptr, nullptr, nullptr, nullptr,
                                               C, M, D, blockIdx.x * 128, 0);
}

// ---------------- edge kernel: scores + vectorized scatter ----------------
__global__ void edge_kernel(const float* __restrict__ Q, const float* __restrict__ Km,
                            const float* __restrict__ V,
                            const int* __restrict__ src, const int* __restrict__ dst,
                            float* __restrict__ wV, float* __restrict__ z, int E)
{
    int gid = blockIdx.x * blockDim.x + threadIdx.x;
    if (gid >= E * H) return;
    int e = gid >> 3;
    int hh = gid & 7;
    int s = src[e];
    int d = dst[e];

    const float4* q = (const float4*)(Q + (size_t)d * D + hh * 16);
    const float4* k = (const float4*)(Km + (size_t)s * D + hh * 16);
    float4 q0 = q[0], q1 = q[1], q2 = q[2], q3 = q[3];
    float4 k0 = k[0], k1 = k[1], k2 = k[2], k3 = k[3];
    float dot = q0.x * k0.x + q0.y * k0.y + q0.z * k0.z + q0.w * k0.w
              + q1.x * k1.x + q1.y * k1.y + q1.z * k1.z + q1.w * k1.w
              + q2.x * k2.x + q2.y * k2.y + q2.z * k2.z + q2.w * k2.w
              + q3.x * k3.x + q3.y * k3.y + q3.z * k3.z + q3.w * k3.w;
    float sc = dot * 0.25f;                 // / sqrt(16)
    sc = fminf(fmaxf(sc, -5.f), 5.f);
    sc = __expf(sc);

    atomicAdd(z + (size_t)d * H + hh, sc);

    const float4* v = (const float4*)(V + (size_t)s * D + hh * 16);
    float* w = wV + (size_t)d * D + hh * 16;
#pragma unroll
    for (int i = 0; i < 4; ++i) {
        float4 vv = v[i];
        asm volatile("red.global.add.v4.f32 [%0], {%1, %2, %3, %4};"
                     :: "l"(w + i * 4),
                        "f"(vv.x * sc), "f"(vv.y * sc), "f"(vv.z * sc), "f"(vv.w * sc)
                     : "memory");
    }
}

// ---------------- batch-norm stats / finalize / apply ----------------
__global__ void bn_stats(const float* __restrict__ x, float* __restrict__ sum,
                         float* __restrict__ sq, int M)
{
    int col = threadIdx.x & (D - 1);
    int sub = threadIdx.x >> 7;   // 0..1
    float s = 0.f, q = 0.f;
    for (int row = blockIdx.x * 2 + sub; row < M; row += gridDim.x * 2) {
        float v = x[(size_t)row * D + col];
        s += v;
        q += v * v;
    }
    __shared__ float shs[D], shq[D];
    if (sub == 1) { shs[col] = s; shq[col] = q; }
    __syncthreads();
    if (sub == 0) {
        atomicAdd(&sum[col], s + shs[col]);
        atomicAdd(&sq[col], q + shq[col]);
    }
}

__global__ void bn_finalize(const float* __restrict__ sum, const float* __restrict__ sq,
                            const float* __restrict__ g, const float* __restrict__ b,
                            float* __restrict__ scale, float* __restrict__ shift, int M)
{
    int c = threadIdx.x;
    float invM = 1.0f / (float)M;
    float mu = sum[c] * invM;
    float var = sq[c] * invM - mu * mu;
    float sc = g[c] * rsqrtf(var + 1e-5f);
    scale[c] = sc;
    shift[c] = b[c] - mu * sc;
}

__global__ void bn_apply(const float* __restrict__ x, const float* __restrict__ bn,
                         float* __restrict__ out, int M)
{
    int tid = blockIdx.x * blockDim.x + threadIdx.x;
    int stride = gridDim.x * blockDim.x;
    int total = M * D;
    for (int i = tid; i < total; i += stride) {
        int c = i & (D - 1);
        out[i] = x[i] * bn[c] + bn[D + c];
    }
}

// ---------------- host launch ----------------
extern "C" void kernel_launch(void* const* d_in, const int* in_sizes, int n_in,
                              void* d_out, int out_size)
{
    const float* h    = (const float*)d_in[0];
    const int*   src  = (const int*)d_in[1];
    const int*   dst  = (const int*)d_in[2];
    const float* WQ   = (const float*)d_in[3];
    const float* WK   = (const float*)d_in[4];
    const float* WV   = (const float*)d_in[5];
    const float* WO   = (const float*)d_in[6];
    const float* bO   = (const float*)d_in[7];
    const float* W1   = (const float*)d_in[8];
    const float* b1   = (const float*)d_in[9];
    const float* W2   = (const float*)d_in[10];
    const float* b2   = (const float*)d_in[11];
    const float* bn1g = (const float*)d_in[12];
    const float* bn1b = (const float*)d_in[13];
    const float* bn2g = (const float*)d_in[14];
    const float* bn2b = (const float*)d_in[15];
    float* out = (float*)d_out;

    int M = in_sizes[0] / D;
    int E = in_sizes[1];
    if (M > N_NODES) M = N_NODES;
    if (E > N_EDGES) E = N_EDGES;

    float *Qp, *Kp, *Vp, *wVp, *zp, *x1p, *midp, *x2p, *stp, *bn1p, *bn2p;
    cudaGetSymbolAddress((void**)&Qp,  g_Q);
    cudaGetSymbolAddress((void**)&Kp,  g_Kf);
    cudaGetSymbolAddress((void**)&Vp,  g_Vf);
    cudaGetSymbolAddress((void**)&wVp, g_wV);
    cudaGetSymbolAddress((void**)&zp,  g_z);
    cudaGetSymbolAddress((void**)&x1p, g_x1);
    cudaGetSymbolAddress((void**)&midp, g_mid);
    cudaGetSymbolAddress((void**)&x2p, g_x2);
    cudaGetSymbolAddress((void**)&stp, g_stats);
    cudaGetSymbolAddress((void**)&bn1p, g_bn1);
    cudaGetSymbolAddress((void**)&bn2p, g_bn2);

    dim3 blk(256);
    int gx = (M + 127) / 128;

    zero_scratch<<<2048, 256>>>();

    // fused QKV projections (one launch, 3x col groups)
    qkv_kernel<<<dim3(gx, 3), blk>>>(h, WQ, WK, WV, Qp, Kp, Vp, M);

    // edge attention scatter
    edge_kernel<<<(E * H + 255) / 256, 256>>>(Qp, Kp, Vp, src, dst, wVp, zp, E);

    // O projection: (wV/z) @ WO^T + bO + h  -> x1
    gemm_k<ATR_DIVZ, EPI_BIAS_RESID, false, 128><<<dim3(gx, 1), blk>>>(
        wVp, WO, bO, h, zp, nullptr, x1p, M, D);

    // BN1 stats
    bn_stats<<<512, 256>>>(x1p, stp, stp + D, M);
    bn_finalize<<<1, D>>>(stp, stp + D, bn1g, bn1b, bn1p, bn1p + D, M);

    // FFN1: relu(BN1(x1) @ W1^T + b1) -> mid  [N, 256]
    gemm_k<ATR_BN, EPI_BIAS_RELU, false, 128><<<dim3(gx, 2), blk>>>(
        x1p, W1, b1, nullptr, bn1p, bn1p + D, midp, M, 2 * D);

    // FFN2: mid @ W2^T + b2 + BN1(x1) -> x2
    gemm_k<ATR_NONE, EPI_BIAS_RESID, true, 256><<<dim3(gx, 1), blk>>>(
        midp, W2, b2, x1p, bn1p, bn1p + D, x2p, M, D);

    // BN2 stats + apply
    bn_stats<<<512, 256>>>(x2p, stp + 2 * D, stp + 3 * D, M);
    bn_finalize<<<1, D>>>(stp + 2 * D, stp + 3 * D, bn2g, bn2b, bn2p, bn2p + D, M);
    bn_apply<<<2048, 256>>>(x2p, bn2p, out, M);
}

// round 4
// speedup vs baseline: 1.4005x; 1.3649x over previous
#include <cuda_runtime.h>
#include <cuda_bf16.h>
#include <math.h>
#include <stdint.h>

#define N_NODES 50000
#define N_EDGES 640000
#define D 128
#define H 8

// ---------------- scratch (static device globals; no allocation) ----------------
__device__ float g_Q [N_NODES * D];
__device__ float g_Kf[N_NODES * D];
__device__ float g_Vf[N_NODES * D];
__device__ float g_wV[N_NODES * D];
__device__ float g_z [N_NODES * H];
__device__ float g_x1[N_NODES * D];
__device__ float g_mid[N_NODES * 2 * D];
__device__ float g_x2[N_NODES * D];
__device__ float g_stats[4 * D];
__device__ float g_bn1[2 * D];
__device__ float g_bn2[2 * D];

// ---------------- helpers ----------------
__device__ __forceinline__ uint32_t smem_u32(const void* p) {
    uint32_t a;
    asm("{ .reg .u64 t; cvta.to.shared.u64 t, %1; cvt.u32.u64 %0, t; }" : "=r"(a) : "l"(p));
    return a;
}
__device__ __forceinline__ void ldm_x4(uint32_t& a0, uint32_t& a1, uint32_t& a2, uint32_t& a3,
                                       uint32_t addr) {
    asm volatile("ldmatrix.sync.aligned.m8n8.x4.shared.b16 {%0,%1,%2,%3}, [%4];"
                 : "=r"(a0), "=r"(a1), "=r"(a2), "=r"(a3) : "r"(addr));
}
__device__ __forceinline__ void ldm_x2(uint32_t& b0, uint32_t& b1, uint32_t addr) {
    asm volatile("ldmatrix.sync.aligned.m8n8.x2.shared.b16 {%0,%1}, [%2];"
                 : "=r"(b0), "=r"(b1) : "r"(addr));
}
__device__ __forceinline__ void mma_bf16(float* c, uint32_t a0, uint32_t a1, uint32_t a2,
                                         uint32_t a3, uint32_t b0, uint32_t b1) {
    asm volatile(
        "mma.sync.aligned.m16n8k16.row.col.f32.bf16.bf16.f32 "
        "{%0,%1,%2,%3}, {%4,%5,%6,%7}, {%8,%9}, {%0,%1,%2,%3};"
        : "+f"(c[0]), "+f"(c[1]), "+f"(c[2]), "+f"(c[3])
        : "r"(a0), "r"(a1), "r"(a2), "r"(a3), "r"(b0), "r"(b1));
}
// split f32 pair -> bf16x2 hi (returned) + bf16x2 lo (out)
__device__ __forceinline__ uint32_t split_pair(float a, float b, uint32_t& lo) {
    uint32_t h;
    asm("cvt.rn.bf16x2.f32 %0, %1, %2;" : "=r"(h) : "f"(b), "f"(a));
    float ra = a - __uint_as_float(h << 16);
    float rb = b - __uint_as_float(h & 0xffff0000u);
    asm("cvt.rn.bf16x2.f32 %0, %1, %2;" : "=r"(lo) : "f"(rb), "f"(ra));
    return h;
}

// ---------------- zero scratch ----------------
__global__ void zero_scratch() {
    int tid = blockIdx.x * blockDim.x + threadIdx.x;
    int stride = gridDim.x * blockDim.x;
    float4 z4 = make_float4(0.f, 0.f, 0.f, 0.f);
    for (int i = tid; i < N_NODES * D / 4; i += stride) ((float4*)g_wV)[i] = z4;
    for (int i = tid; i < N_NODES * H / 4; i += stride) ((float4*)g_z)[i] = z4;
    if (tid < 4 * D) g_stats[tid] = 0.f;
}

// ---------------- tensor-core GEMM via mma.sync: C = op(A)[M,KT] @ W[*,KT]^T -----
enum { ATR_NONE = 0, ATR_DIVZ = 1, ATR_BN = 2 };
enum { EPI_STORE = 0, EPI_BIAS_RESID = 1, EPI_BIAS_RELU = 2 };

#define SK 72                       // padded bf16 stride per row
#define TILE_E (128 * SK)           // elements per tile buffer
#define TILE_BYTES (TILE_E * 2)     // 18432 B
#define DSMEM_BYTES (4 * TILE_BYTES)

template <int ATR, int EPI, bool RESBN, int KT>
__device__ __forceinline__ void tgemm_core(
    const float* __restrict__ A, const float* __restrict__ W,
    const float* __restrict__ bias, const float* __restrict__ resid,
    const float* __restrict__ t0, const float* __restrict__ t1,
    float* __restrict__ C, int M, int ldc, int rowBase, int colBase)
{
    extern __shared__ __align__(16) char sm[];
    char* sAhi = sm;
    char* sAlo = sm + TILE_BYTES;
    char* sWhi = sm + 2 * TILE_BYTES;
    char* sWlo = sm + 3 * TILE_BYTES;

    const int tid = threadIdx.x;
    const int wid = tid >> 5;
    const int lid = tid & 31;
    const int warp_m = wid & 1;   // 2 row groups of 64
    const int warp_n = wid >> 1;  // 4 col groups of 32

    // ldmatrix lane offsets
    const int ar = (lid & 7) + ((lid >> 3) & 1) * 8;  // A row within 16
    const int ac = (lid >> 4) * 8;                    // A col within 16
    const int br = lid & 7;                           // B row within 8
    const int bc = ((lid >> 3) & 1) * 8;              // B col within 16

    const uint32_t saHi = smem_u32(sAhi), saLo = smem_u32(sAlo);
    const uint32_t swHi = smem_u32(sWhi), swLo = smem_u32(sWlo);
    const uint32_t aOff = (uint32_t)((warp_m * 64 + ar) * SK + ac) * 2;
    const uint32_t bOff = (uint32_t)((warp_n * 32 + br) * SK + bc) * 2;

    float acc[4][4][4];
#pragma unroll
    for (int i = 0; i < 4; ++i)
#pragma unroll
        for (int j = 0; j < 4; ++j)
#pragma unroll
            for (int t = 0; t < 4; ++t) acc[i][j][t] = 0.f;

    const int row = tid >> 1;         // 0..127
    const int kh = (tid & 1) * 32;    // 32-col half of the 64-wide slab
    const int grow = rowBase + row;
    const bool valid = grow < M;

    constexpr int NSLAB = KT / 64;
#pragma unroll
    for (int slab = 0; slab < NSLAB; ++slab) {
        const int slabK = slab * 64;
        // ---- convert A (with transform) and W into hi/lo bf16 tiles ----
        {
            const float* Ar = A + (size_t)grow * KT + slabK + kh;
#pragma unroll
            for (int g = 0; g < 4; ++g) {
                float4 f0 = make_float4(0.f, 0.f, 0.f, 0.f), f1 = f0;
                if (valid) {
                    f0 = *(const float4*)(Ar + g * 8);
                    f1 = *(const float4*)(Ar + g * 8 + 4);
                    int kg = slabK + kh + g * 8;
                    if (ATR == ATR_DIVZ) {
                        float iz = 1.0f / t0[grow * H + (kg >> 4)];
                        f0.x *= iz; f0.y *= iz; f0.z *= iz; f0.w *= iz;
                        f1.x *= iz; f1.y *= iz; f1.z *= iz; f1.w *= iz;
                    } else if (ATR == ATR_BN) {
                        float4 sc0 = *(const float4*)(t0 + kg);
                        float4 sc1 = *(const float4*)(t0 + kg + 4);
                        float4 sh0 = *(const float4*)(t1 + kg);
                        float4 sh1 = *(const float4*)(t1 + kg + 4);
                        f0.x = f0.x * sc0.x + sh0.x; f0.y = f0.y * sc0.y + sh0.y;
                        f0.z = f0.z * sc0.z + sh0.z; f0.w = f0.w * sc0.w + sh0.w;
                        f1.x = f1.x * sc1.x + sh1.x; f1.y = f1.y * sc1.y + sh1.y;
                        f1.z = f1.z * sc1.z + sh1.z; f1.w = f1.w * sc1.w + sh1.w;
                    }
                }
                uint4 hi, lo;
                hi.x = split_pair(f0.x, f0.y, lo.x);
                hi.y = split_pair(f0.z, f0.w, lo.y);
                hi.z = split_pair(f1.x, f1.y, lo.z);
                hi.w = split_pair(f1.z, f1.w, lo.w);
                uint32_t off = (uint32_t)(row * SK + kh + g * 8) * 2;
                *(uint4*)(sAhi + off) = hi;
                *(uint4*)(sAlo + off) = lo;
            }
            const float* Wr = W + (size_t)(colBase + row) * KT + slabK + kh;
#pragma unroll
            for (int g = 0; g < 4; ++g) {
                float4 f0 = *(const float4*)(Wr + g * 8);
                float4 f1 = *(const float4*)(Wr + g * 8 + 4);
                uint4 hi, lo;
                hi.x = split_pair(f0.x, f0.y, lo.x);
                hi.y = split_pair(f0.z, f0.w, lo.y);
                hi.z = split_pair(f1.x, f1.y, lo.z);
                hi.w = split_pair(f1.z, f1.w, lo.w);
                uint32_t off = (uint32_t)(row * SK + kh + g * 8) * 2;
                *(uint4*)(sWhi + off) = hi;
                *(uint4*)(sWlo + off) = lo;
            }
        }
        __syncthreads();

        // ---- mma phase ----
#pragma unroll
        for (int ks = 0; ks < 4; ++ks) {
            const uint32_t k0 = (uint32_t)(ks * 16) * 2;
            uint32_t bh[4][2], bl[4][2];
#pragma unroll
            for (int j = 0; j < 4; ++j) {
                uint32_t boff = bOff + (uint32_t)(j * 8 * SK) * 2 + k0;
                ldm_x2(bh[j][0], bh[j][1], swHi + boff);
                ldm_x2(bl[j][0], bl[j][1], swLo + boff);
            }
#pragma unroll
            for (int i = 0; i < 4; ++i) {
                uint32_t aoff = aOff + (uint32_t)(i * 16 * SK) * 2 + k0;
                uint32_t ah0, ah1, ah2, ah3, al0, al1, al2, al3;
                ldm_x4(ah0, ah1, ah2, ah3, saHi + aoff);
                ldm_x4(al0, al1, al2, al3, saLo + aoff);
#pragma unroll
                for (int j = 0; j < 4; ++j) {
                    mma_bf16(acc[i][j], ah0, ah1, ah2, ah3, bh[j][0], bh[j][1]);
                    mma_bf16(acc[i][j], ah0, ah1, ah2, ah3, bl[j][0], bl[j][1]);
                    mma_bf16(acc[i][j], al0, al1, al2, al3, bh[j][0], bh[j][1]);
                }
            }
        }
        if (slab + 1 < NSLAB) __syncthreads();
    }

    // ---- epilogue ----
    const int rr = lid >> 2;
    const int cc = (lid & 3) * 2;
#pragma unroll
    for (int i = 0; i < 4; ++i) {
#pragma unroll
        for (int half = 0; half < 2; ++half) {
            int r = rowBase + warp_m * 64 + i * 16 + rr + half * 8;
            if (r >= M) continue;
            float* Crow = C + (size_t)r * ldc;
            const float* Rrow = resid ? resid + (size_t)r * D : nullptr;
#pragma unroll
            for (int j = 0; j < 4; ++j) {
                int col = colBase + warp_n * 32 + j * 8 + cc;
                float v0 = acc[i][j][half * 2];
                float v1 = acc[i][j][half * 2 + 1];
                if (EPI == EPI_BIAS_RESID) {
                    v0 += bias[col];
                    v1 += bias[col + 1];
                    float r0 = Rrow[col], r1 = Rrow[col + 1];
                    if (RESBN) {
                        r0 = r0 * t0[col] + t1[col];
                        r1 = r1 * t0[col + 1] + t1[col + 1];
                    }
                    v0 += r0; v1 += r1;
                } else if (EPI == EPI_BIAS_RELU) {
                    v0 = fmaxf(v0 + bias[col], 0.f);
                    v1 = fmaxf(v1 + bias[col + 1], 0.f);
                }
                *(float2*)(Crow + col) = make_float2(v0, v1);
            }
        }
    }
}

template <int ATR, int EPI, bool RESBN, int KT>
__global__ __launch_bounds__(256, 2) void tgemm_k(
    const float* __restrict__ A, const float* __restrict__ W,
    const float* __restrict__ bias, const float* __restrict__ resid,
    const float* __restrict__ t0, const float* __restrict__ t1,
    float* __restrict__ C, int M, int ldc)
{
    tgemm_core<ATR, EPI, RESBN, KT>(A, W, bias, resid, t0, t1, C, M, ldc,
                                    blockIdx.x * 128, blockIdx.y * 128);
}

__global__ __launch_bounds__(256, 2) void qkv_kernel(
    const float* __restrict__ h,
    const float* __restrict__ WQ, const float* __restrict__ WK, const float* __restrict__ WV,
    float* __restrict__ Q, float* __restrict__ K, float* __restrict__ V, int M)
{
    const float* W = (blockIdx.y == 0) ? WQ : (blockIdx.y == 1) ? WK : WV;
    float* C = (blockIdx.y == 0) ? Q : (blockIdx.y == 1) ? K : V;
    tgemm_core<ATR_NONE, EPI_STORE, false, 128>(h, W, nullptr, nullptr, nullptr, nullptr,
                                                C, M, D, blockIdx.x * 128, 0);
}

// ---------------- edge kernel ----------------
__global__ void edge_kernel(const float* __restrict__ Q, const float* __restrict__ Km,
                            const float* __restrict__ V,
                            const int* __restrict__ src, const int* __restrict__ dst,
                            float* __restrict__ wV, float* __restrict__ z, int E)
{
    int gid = blockIdx.x * blockDim.x + threadIdx.x;
    if (gid >= E * H) return;
    int e = gid >> 3;
    int hh = gid & 7;
    int s = src[e];
    int d = dst[e];

    const float4* q = (const float4*)(Q + (size_t)d * D + hh * 16);
    const float4* k = (const float4*)(Km + (size_t)s * D + hh * 16);
    float4 q0 = q[0], q1 = q[1], q2 = q[2], q3 = q[3];
    float4 k0 = k[0], k1 = k[1], k2 = k[2], k3 = k[3];
    float dot = q0.x * k0.x + q0.y * k0.y + q0.z * k0.z + q0.w * k0.w
              + q1.x * k1.x + q1.y * k1.y + q1.z * k1.z + q1.w * k1.w
              + q2.x * k2.x + q2.y * k2.y + q2.z * k2.z + q2.w * k2.w
              + q3.x * k3.x + q3.y * k3.y + q3.z * k3.z + q3.w * k3.w;
    float sc = dot * 0.25f;
    sc = fminf(fmaxf(sc, -5.f), 5.f);
    sc = __expf(sc);

    atomicAdd(z + (size_t)d * H + hh, sc);

    const float4* v = (const float4*)(V + (size_t)s * D + hh * 16);
    float* w = wV + (size_t)d * D + hh * 16;
#pragma unroll
    for (int i = 0; i < 4; ++i) {
        float4 vv = v[i];
        asm volatile("red.global.add.v4.f32 [%0], {%1, %2, %3, %4};"
                     :: "l"(w + i * 4),
                        "f"(vv.x * sc), "f"(vv.y * sc), "f"(vv.z * sc), "f"(vv.w * sc)
                     : "memory");
    }
}

// ---------------- batch-norm ----------------
__global__ void bn_stats(const float* __restrict__ x, float* __restrict__ sum,
                         float* __restrict__ sq, int M)
{
    int col = threadIdx.x & (D - 1);
    int sub = threadIdx.x >> 7;
    float s = 0.f, q = 0.f;
    for (int row = blockIdx.x * 2 + sub; row < M; row += gridDim.x * 2) {
        float v = x[(size_t)row * D + col];
        s += v;
        q += v * v;
    }
    __shared__ float shs[D], shq[D];
    if (sub == 1) { shs[col] = s; shq[col] = q; }
    __syncthreads();
    if (sub == 0) {
        atomicAdd(&sum[col], s + shs[col]);
        atomicAdd(&sq[col], q + shq[col]);
    }
}

__global__ void bn_finalize(const float* __restrict__ sum, const float* __restrict__ sq,
                            const float* __restrict__ g, const float* __restrict__ b,
                            float* __restrict__ scale, float* __restrict__ shift, int M)
{
    int c = threadIdx.x;
    float invM = 1.0f / (float)M;
    float mu = sum[c] * invM;
    float var = sq[c] * invM - mu * mu;
    float sc = g[c] * rsqrtf(var + 1e-5f);
    scale[c] = sc;
    shift[c] = b[c] - mu * sc;
}

__global__ void bn_apply(const float* __restrict__ x, const float* __restrict__ bn,
                         float* __restrict__ out, int M)
{
    int tid = blockIdx.x * blockDim.x + threadIdx.x;
    int stride = gridDim.x * blockDim.x;
    int total = M * D;
    for (int i = tid; i < total; i += stride) {
        int c = i & (D - 1);
        out[i] = x[i] * bn[c] + bn[D + c];
    }
}

// ---------------- host launch ----------------
extern "C" void kernel_launch(void* const* d_in, const int* in_sizes, int n_in,
                              void* d_out, int out_size)
{
    const float* h    = (const float*)d_in[0];
    const int*   src  = (const int*)d_in[1];
    const int*   dst  = (const int*)d_in[2];
    const float* WQ   = (const float*)d_in[3];
    const float* WK   = (const float*)d_in[4];
    const float* WV   = (const float*)d_in[5];
    const float* WO   = (const float*)d_in[6];
    const float* bO   = (const float*)d_in[7];
    const float* W1   = (const float*)d_in[8];
    const float* b1   = (const float*)d_in[9];
    const float* W2   = (const float*)d_in[10];
    const float* b2   = (const float*)d_in[11];
    const float* bn1g = (const float*)d_in[12];
    const float* bn1b = (const float*)d_in[13];
    const float* bn2g = (const float*)d_in[14];
    const float* bn2b = (const float*)d_in[15];
    float* out = (float*)d_out;

    int M = in_sizes[0] / D;
    int E = in_sizes[1];
    if (M > N_NODES) M = N_NODES;
    if (E > N_EDGES) E = N_EDGES;

    float *Qp, *Kp, *Vp, *wVp, *zp, *x1p, *midp, *x2p, *stp, *bn1p, *bn2p;
    cudaGetSymbolAddress((void**)&Qp,  g_Q);
    cudaGetSymbolAddress((void**)&Kp,  g_Kf);
    cudaGetSymbolAddress((void**)&Vp,  g_Vf);
    cudaGetSymbolAddress((void**)&wVp, g_wV);
    cudaGetSymbolAddress((void**)&zp,  g_z);
    cudaGetSymbolAddress((void**)&x1p, g_x1);
    cudaGetSymbolAddress((void**)&midp, g_mid);
    cudaGetSymbolAddress((void**)&x2p, g_x2);
    cudaGetSymbolAddress((void**)&stp, g_stats);
    cudaGetSymbolAddress((void**)&bn1p, g_bn1);
    cudaGetSymbolAddress((void**)&bn2p, g_bn2);

    cudaFuncSetAttribute(qkv_kernel, cudaFuncAttributeMaxDynamicSharedMemorySize, DSMEM_BYTES);
    cudaFuncSetAttribute(tgemm_k<ATR_DIVZ, EPI_BIAS_RESID, false, 128>,
                         cudaFuncAttributeMaxDynamicSharedMemorySize, DSMEM_BYTES);
    cudaFuncSetAttribute(tgemm_k<ATR_BN, EPI_BIAS_RELU, false, 128>,
                         cudaFuncAttributeMaxDynamicSharedMemorySize, DSMEM_BYTES);
    cudaFuncSetAttribute(tgemm_k<ATR_NONE, EPI_BIAS_RESID, true, 256>,
                         cudaFuncAttributeMaxDynamicSharedMemorySize, DSMEM_BYTES);

    dim3 blk(256);
    int gx = (M + 127) / 128;

    zero_scratch<<<2048, 256>>>();

    // fused QKV projections
    qkv_kernel<<<dim3(gx, 3), blk, DSMEM_BYTES>>>(h, WQ, WK, WV, Qp, Kp, Vp, M);

    // edge attention scatter
    edge_kernel<<<(E * H + 255) / 256, 256>>>(Qp, Kp, Vp, src, dst, wVp, zp, E);

    // O projection: (wV/z) @ WO^T + bO + h -> x1
    tgemm_k<ATR_DIVZ, EPI_BIAS_RESID, false, 128><<<dim3(gx, 1), blk, DSMEM_BYTES>>>(
        wVp, WO, bO, h, zp, nullptr, x1p, M, D);

    // BN1
    bn_stats<<<512, 256>>>(x1p, stp, stp + D, M);
    bn_finalize<<<1, D>>>(stp, stp + D, bn1g, bn1b, bn1p, bn1p + D, M);

    // FFN1: relu(BN1(x1) @ W1^T + b1) -> mid [N, 256]
    tgemm_k<ATR_BN, EPI_BIAS_RELU, false, 128><<<dim3(gx, 2), blk, DSMEM_BYTES>>>(
        x1p, W1, b1, nullptr, bn1p, bn1p + D, midp, M, 2 * D);

    // FFN2: mid @ W2^T + b2 + BN1(x1) -> x2
    tgemm_k<ATR_NONE, EPI_BIAS_RESID, true, 256><<<dim3(gx, 1), blk, DSMEM_BYTES>>>(
        midp, W2, b2, x1p, bn1p, bn1p + D, x2p, M, D);

    // BN2
    bn_stats<<<512, 256>>>(x2p, stp + 2 * D, stp + 3 * D, M);
    bn_finalize<<<1, D>>>(stp + 2 * D, stp + 3 * D, bn2g, bn2b, bn2p, bn2p + D, M);
    bn_apply<<<2048, 256>>>(x2p, bn2p, out, M);
}

// round 5
// speedup vs baseline: 1.5568x; 1.1115x over previous
#include <cuda_runtime.h>
#include <cuda_bf16.h>
#include <math.h>
#include <stdint.h>

#define N_NODES 50000
#define N_EDGES 640000
#define D 128
#define H 8

// ---------------- scratch (static device globals; no allocation) ----------------
__device__ float g_Q [N_NODES * D];
__device__ float g_Kf[N_NODES * D];
__device__ float g_Vf[N_NODES * D];
__device__ float g_wV[N_NODES * D];
__device__ float g_z [N_NODES * H];
__device__ float g_x1[N_NODES * D];
__device__ float g_mid[N_NODES * 2 * D];
__device__ float g_x2[N_NODES * D];
__device__ float g_stats[4 * D];
__device__ float g_bn1[2 * D];
__device__ float g_bn2[2 * D];
// pre-converted weights: hi and lo bf16, same row-major layout as fp32 source
#define W_TOTAL 131072  // 4*128*128 + 256*128 + 128*256
__device__ __nv_bfloat16 g_wh[W_TOTAL];
__device__ __nv_bfloat16 g_wl[W_TOTAL];
// element offsets of each matrix inside the concatenated buffer
#define OFF_WQ 0
#define OFF_WK 16384
#define OFF_WV 32768
#define OFF_WO 49152
#define OFF_W1 65536
#define OFF_W2 98304

// ---------------- helpers ----------------
__device__ __forceinline__ uint32_t smem_u32(const void* p) {
    uint32_t a;
    asm("{ .reg .u64 t; cvta.to.shared.u64 t, %1; cvt.u32.u64 %0, t; }" : "=r"(a) : "l"(p));
    return a;
}
__device__ __forceinline__ void ldm_x4(uint32_t& a0, uint32_t& a1, uint32_t& a2, uint32_t& a3,
                                       uint32_t addr) {
    asm volatile("ldmatrix.sync.aligned.m8n8.x4.shared.b16 {%0,%1,%2,%3}, [%4];"
                 : "=r"(a0), "=r"(a1), "=r"(a2), "=r"(a3) : "r"(addr));
}
__device__ __forceinline__ void ldm_x2(uint32_t& b0, uint32_t& b1, uint32_t addr) {
    asm volatile("ldmatrix.sync.aligned.m8n8.x2.shared.b16 {%0,%1}, [%2];"
                 : "=r"(b0), "=r"(b1) : "r"(addr));
}
__device__ __forceinline__ void mma_bf16(float* c, uint32_t a0, uint32_t a1, uint32_t a2,
                                         uint32_t a3, uint32_t b0, uint32_t b1) {
    asm volatile(
        "mma.sync.aligned.m16n8k16.row.col.f32.bf16.bf16.f32 "
        "{%0,%1,%2,%3}, {%4,%5,%6,%7}, {%8,%9}, {%0,%1,%2,%3};"
        : "+f"(c[0]), "+f"(c[1]), "+f"(c[2]), "+f"(c[3])
        : "r"(a0), "r"(a1), "r"(a2), "r"(a3), "r"(b0), "r"(b1));
}
__device__ __forceinline__ uint32_t split_pair(float a, float b, uint32_t& lo) {
    uint32_t h;
    asm("cvt.rn.bf16x2.f32 %0, %1, %2;" : "=r"(h) : "f"(b), "f"(a));
    float ra = a - __uint_as_float(h << 16);
    float rb = b - __uint_as_float(h & 0xffff0000u);
    asm("cvt.rn.bf16x2.f32 %0, %1, %2;" : "=r"(lo) : "f"(rb), "f"(ra));
    return h;
}
__device__ __forceinline__ void cp16(uint32_t dst, const void* src) {
    asm volatile("cp.async.cg.shared.global [%0], [%1], 16;" :: "r"(dst), "l"(src));
}
#define CP_COMMIT() asm volatile("cp.async.commit_group;" ::: "memory")
#define CP_WAIT0()  asm volatile("cp.async.wait_group 0;" ::: "memory")

// ---------------- weight conversion (once per replay, ~3us) ----------------
__global__ void convert_weights(const float* __restrict__ WQ, const float* __restrict__ WK,
                                const float* __restrict__ WV, const float* __restrict__ WO,
                                const float* __restrict__ W1, const float* __restrict__ W2)
{
    int p = blockIdx.x * blockDim.x + threadIdx.x;   // pair index
    if (p >= W_TOTAL / 2) return;
    int elem = p * 2;
    const float* src;
    int local;
    if (elem < OFF_W1) {
        int m = elem >> 14;
        local = elem & 16383;
        src = (m == 0) ? WQ : (m == 1) ? WK : (m == 2) ? WV : WO;
    } else if (elem < OFF_W2) {
        local = elem - OFF_W1;
        src = W1;
    } else {
        local = elem - OFF_W2;
        src = W2;
    }
    float a = src[local], b = src[local + 1];
    uint32_t lo;
    uint32_t hi = split_pair(a, b, lo);
    ((uint32_t*)g_wh)[p] = hi;
    ((uint32_t*)g_wl)[p] = lo;
}

// ---------------- zero scratch ----------------
__global__ void zero_scratch() {
    int tid = blockIdx.x * blockDim.x + threadIdx.x;
    int stride = gridDim.x * blockDim.x;
    float4 z4 = make_float4(0.f, 0.f, 0.f, 0.f);
    for (int i = tid; i < N_NODES * D / 4; i += stride) ((float4*)g_wV)[i] = z4;
    for (int i = tid; i < N_NODES * H / 4; i += stride) ((float4*)g_z)[i] = z4;
    if (tid < 4 * D) g_stats[tid] = 0.f;
}

// ---------------- tensor-core GEMM: C = op(A)[M,KT] @ W[*,KT]^T -----------------
enum { ATR_NONE = 0, ATR_DIVZ = 1, ATR_BN = 2 };
enum { EPI_STORE = 0, EPI_BIAS_RESID = 1, EPI_BIAS_RELU = 2 };

#define SK 72
#define TILE_BYTES (128 * SK * 2)
#define DSMEM_BYTES (4 * TILE_BYTES)

template <int ATR, int EPI, bool RESBN, bool STATS, int KT>
__device__ __forceinline__ void tgemm_core(
    const float* __restrict__ A,
    const __nv_bfloat16* __restrict__ Wh, const __nv_bfloat16* __restrict__ Wl,
    const float* __restrict__ bias, const float* __restrict__ resid,
    const float* __restrict__ t0, const float* __restrict__ t1,
    float* __restrict__ ssum, float* __restrict__ ssq,
    float* __restrict__ C, int M, int ldc, int rowBase, int colBase)
{
    extern __shared__ __align__(16) char sm[];
    char* sAhi = sm;
    char* sAlo = sm + TILE_BYTES;
    char* sWhi = sm + 2 * TILE_BYTES;
    char* sWlo = sm + 3 * TILE_BYTES;

    const int tid = threadIdx.x;
    const int wid = tid >> 5;
    const int lid = tid & 31;
    const int warp_m = wid & 1;
    const int warp_n = wid >> 1;

    const int ar = (lid & 7) + ((lid >> 3) & 1) * 8;
    const int ac = (lid >> 4) * 8;
    const int br = lid & 7;
    const int bc = ((lid >> 3) & 1) * 8;

    const uint32_t saHi = smem_u32(sAhi), saLo = smem_u32(sAlo);
    const uint32_t swHi = smem_u32(sWhi), swLo = smem_u32(sWlo);
    const uint32_t aOff = (uint32_t)((warp_m * 64 + ar) * SK + ac) * 2;
    const uint32_t bOff = (uint32_t)((warp_n * 32 + br) * SK + bc) * 2;

    float acc[4][4][4];
#pragma unroll
    for (int i = 0; i < 4; ++i)
#pragma unroll
        for (int j = 0; j < 4; ++j)
#pragma unroll
            for (int t = 0; t < 4; ++t) acc[i][j][t] = 0.f;

    const int row = tid >> 1;
    const int kh = (tid & 1) * 32;
    const int grow = rowBase + row;
    const bool valid = grow < M;

    constexpr int NSLAB = KT / 64;
#pragma unroll
    for (int slab = 0; slab < NSLAB; ++slab) {
        const int slabK = slab * 64;

        // ---- W slab: direct bf16 cp.async (overlaps with A convert below) ----
        {
            const __nv_bfloat16* Whp = Wh + (size_t)(colBase + row) * KT + slabK + kh;
            const __nv_bfloat16* Wlp = Wl + (size_t)(colBase + row) * KT + slabK + kh;
            uint32_t dh = swHi + (uint32_t)(row * SK + kh) * 2;
            uint32_t dl = swLo + (uint32_t)(row * SK + kh) * 2;
#pragma unroll
            for (int c = 0; c < 4; ++c) cp16(dh + c * 16, Whp + c * 8);
#pragma unroll
            for (int c = 0; c < 4; ++c) cp16(dl + c * 16, Wlp + c * 8);
            CP_COMMIT();
        }

        // ---- convert A slab ----
        {
            const float* Ar = A + (size_t)grow * KT + slabK + kh;
#pragma unroll
            for (int g = 0; g < 4; ++g) {
                float4 f0 = make_float4(0.f, 0.f, 0.f, 0.f), f1 = f0;
                if (valid) {
                    f0 = *(const float4*)(Ar + g * 8);
                    f1 = *(const float4*)(Ar + g * 8 + 4);
                    int kg = slabK + kh + g * 8;
                    if (ATR == ATR_DIVZ) {
                        float iz = 1.0f / t0[grow * H + (kg >> 4)];
                        f0.x *= iz; f0.y *= iz; f0.z *= iz; f0.w *= iz;
                        f1.x *= iz; f1.y *= iz; f1.z *= iz; f1.w *= iz;
                    } else if (ATR == ATR_BN) {
                        float4 sc0 = *(const float4*)(t0 + kg);
                        float4 sc1 = *(const float4*)(t0 + kg + 4);
                        float4 sh0 = *(const float4*)(t1 + kg);
                        float4 sh1 = *(const float4*)(t1 + kg + 4);
                        f0.x = f0.x * sc0.x + sh0.x; f0.y = f0.y * sc0.y + sh0.y;
                        f0.z = f0.z * sc0.z + sh0.z; f0.w = f0.w * sc0.w + sh0.w;
                        f1.x = f1.x * sc1.x + sh1.x; f1.y = f1.y * sc1.y + sh1.y;
                        f1.z = f1.z * sc1.z + sh1.z; f1.w = f1.w * sc1.w + sh1.w;
                    }
                }
                uint4 hi, lo;
                hi.x = split_pair(f0.x, f0.y, lo.x);
                hi.y = split_pair(f0.z, f0.w, lo.y);
                hi.z = split_pair(f1.x, f1.y, lo.z);
                hi.w = split_pair(f1.z, f1.w, lo.w);
                uint32_t off = (uint32_t)(row * SK + kh + g * 8) * 2;
                *(uint4*)(sAhi + off) = hi;
                *(uint4*)(sAlo + off) = lo;
            }
        }
        CP_WAIT0();
        __syncthreads();

        // ---- mma phase ----
#pragma unroll
        for (int ks = 0; ks < 4; ++ks) {
            const uint32_t k0 = (uint32_t)(ks * 16) * 2;
            uint32_t bh[4][2], bl[4][2];
#pragma unroll
            for (int j = 0; j < 4; ++j) {
                uint32_t boff = bOff + (uint32_t)(j * 8 * SK) * 2 + k0;
                ldm_x2(bh[j][0], bh[j][1], swHi + boff);
                ldm_x2(bl[j][0], bl[j][1], swLo + boff);
            }
#pragma unroll
            for (int i = 0; i < 4; ++i) {
                uint32_t aoff = aOff + (uint32_t)(i * 16 * SK) * 2 + k0;
                uint32_t ah0, ah1, ah2, ah3, al0, al1, al2, al3;
                ldm_x4(ah0, ah1, ah2, ah3, saHi + aoff);
                ldm_x4(al0, al1, al2, al3, saLo + aoff);
#pragma unroll
                for (int j = 0; j < 4; ++j) {
                    mma_bf16(acc[i][j], ah0, ah1, ah2, ah3, bh[j][0], bh[j][1]);
                    mma_bf16(acc[i][j], ah0, ah1, ah2, ah3, bl[j][0], bl[j][1]);
                    mma_bf16(acc[i][j], al0, al1, al2, al3, bh[j][0], bh[j][1]);
                }
            }
        }
        if (slab + 1 < NSLAB) __syncthreads();
    }

    // ---- epilogue (+ optional fused BN stats) ----
    const int rr = lid >> 2;
    const int cc = (lid & 3) * 2;
    float cs[8], cq[8];
    if (STATS) {
#pragma unroll
        for (int t = 0; t < 8; ++t) { cs[t] = 0.f; cq[t] = 0.f; }
    }
#pragma unroll
    for (int i = 0; i < 4; ++i) {
#pragma unroll
        for (int half = 0; half < 2; ++half) {
            int r = rowBase + warp_m * 64 + i * 16 + rr + half * 8;
            if (r >= M) continue;
            float* Crow = C + (size_t)r * ldc;
            const float* Rrow = resid ? resid + (size_t)r * D : nullptr;
#pragma unroll
            for (int j = 0; j < 4; ++j) {
                int col = colBase + warp_n * 32 + j * 8 + cc;
                float v0 = acc[i][j][half * 2];
                float v1 = acc[i][j][half * 2 + 1];
                if (EPI == EPI_BIAS_RESID) {
                    v0 += bias[col];
                    v1 += bias[col + 1];
                    float r0 = Rrow[col], r1 = Rrow[col + 1];
                    if (RESBN) {
                        r0 = r0 * t0[col] + t1[col];
                        r1 = r1 * t0[col + 1] + t1[col + 1];
                    }
                    v0 += r0; v1 += r1;
                } else if (EPI == EPI_BIAS_RELU) {
                    v0 = fmaxf(v0 + bias[col], 0.f);
                    v1 = fmaxf(v1 + bias[col + 1], 0.f);
                }
                if (STATS) {
                    cs[j * 2] += v0;     cq[j * 2] += v0 * v0;
                    cs[j * 2 + 1] += v1; cq[j * 2 + 1] += v1 * v1;
                }
                *(float2*)(Crow + col) = make_float2(v0, v1);
            }
        }
    }
    if (STATS) {
#pragma unroll
        for (int t = 0; t < 8; ++t) {
#pragma unroll
            for (int o = 4; o < 32; o <<= 1) {
                cs[t] += __shfl_xor_sync(0xffffffffu, cs[t], o);
                cq[t] += __shfl_xor_sync(0xffffffffu, cq[t], o);
            }
        }
        if (lid < 4) {
#pragma unroll
            for (int t = 0; t < 8; ++t) {
                int col = colBase + warp_n * 32 + (t >> 1) * 8 + lid * 2 + (t & 1);
                atomicAdd(&ssum[col & (D - 1)], cs[t]);
                atomicAdd(&ssq[col & (D - 1)], cq[t]);
            }
        }
    }
}

template <int ATR, int EPI, bool RESBN, bool STATS, int KT>
__global__ __launch_bounds__(256, 2) void tgemm_k(
    const float* __restrict__ A,
    const __nv_bfloat16* __restrict__ Wh, const __nv_bfloat16* __restrict__ Wl,
    const float* __restrict__ bias, const float* __restrict__ resid,
    const float* __restrict__ t0, const float* __restrict__ t1,
    float* __restrict__ ssum, float* __restrict__ ssq,
    float* __restrict__ C, int M, int ldc)
{
    tgemm_core<ATR, EPI, RESBN, STATS, KT>(A, Wh, Wl, bias, resid, t0, t1, ssum, ssq,
                                           C, M, ldc, blockIdx.x * 128, blockIdx.y * 128);
}

__global__ __launch_bounds__(256, 2) void qkv_kernel(
    const float* __restrict__ h,
    float* __restrict__ Q, float* __restrict__ K, float* __restrict__ V, int M)
{
    int off = (blockIdx.y == 0) ? OFF_WQ : (blockIdx.y == 1) ? OFF_WK : OFF_WV;
    float* C = (blockIdx.y == 0) ? Q : (blockIdx.y == 1) ? K : V;
    tgemm_core<ATR_NONE, EPI_STORE, false, false, 128>(
        h, g_wh + off, g_wl + off, nullptr, nullptr, nullptr, nullptr, nullptr, nullptr,
        C, M, D, blockIdx.x * 128, 0);
}

// ---------------- edge kernel ----------------
__global__ void edge_kernel(const float* __restrict__ Q, const float* __restrict__ Km,
                            const float* __restrict__ V,
                            const int* __restrict__ src, const int* __restrict__ dst,
                            float* __restrict__ wV, float* __restrict__ z, int E)
{
    int gid = blockIdx.x * blockDim.x + threadIdx.x;
    if (gid >= E * H) return;
    int e = gid >> 3;
    int hh = gid & 7;
    int s = src[e];
    int d = dst[e];

    const float4* q = (const float4*)(Q + (size_t)d * D + hh * 16);
    const float4* k = (const float4*)(Km + (size_t)s * D + hh * 16);
    float4 q0 = q[0], q1 = q[1], q2 = q[2], q3 = q[3];
    float4 k0 = k[0], k1 = k[1], k2 = k[2], k3 = k[3];
    float dot = q0.x * k0.x + q0.y * k0.y + q0.z * k0.z + q0.w * k0.w
              + q1.x * k1.x + q1.y * k1.y + q1.z * k1.z + q1.w * k1.w
              + q2.x * k2.x + q2.y * k2.y + q2.z * k2.z + q2.w * k2.w
              + q3.x * k3.x + q3.y * k3.y + q3.z * k3.z + q3.w * k3.w;
    float sc = dot * 0.25f;
    sc = fminf(fmaxf(sc, -5.f), 5.f);
    sc = __expf(sc);

    atomicAdd(z + (size_t)d * H + hh, sc);

    const float4* v = (const float4*)(V + (size_t)s * D + hh * 16);
    float* w = wV + (size_t)d * D + hh * 16;
#pragma unroll
    for (int i = 0; i < 4; ++i) {
        float4 vv = v[i];
        asm volatile("red.global.add.v4.f32 [%0], {%1, %2, %3, %4};"
                     :: "l"(w + i * 4),
                        "f"(vv.x * sc), "f"(vv.y * sc), "f"(vv.z * sc), "f"(vv.w * sc)
                     : "memory");
    }
}

// ---------------- batch-norm finalize/apply ----------------
__global__ void bn_finalize(const float* __restrict__ sum, const float* __restrict__ sq,
                            const float* __restrict__ g, const float* __restrict__ b,
                            float* __restrict__ scale, float* __restrict__ shift, int M)
{
    int c = threadIdx.x;
    float invM = 1.0f / (float)M;
    float mu = sum[c] * invM;
    float var = sq[c] * invM - mu * mu;
    float sc = g[c] * rsqrtf(var + 1e-5f);
    scale[c] = sc;
    shift[c] = b[c] - mu * sc;
}

__global__ void bn_apply(const float* __restrict__ x, const float* __restrict__ bn,
                         float* __restrict__ out, int M)
{
    int tid = blockIdx.x * blockDim.x + threadIdx.x;
    int stride = gridDim.x * blockDim.x;
    int total = M * D;
    for (int i = tid; i < total; i += stride) {
        int c = i & (D - 1);
        out[i] = x[i] * bn[c] + bn[D + c];
    }
}

// ---------------- host launch ----------------
extern "C" void kernel_launch(void* const* d_in, const int* in_sizes, int n_in,
                              void* d_out, int out_size)
{
    const float* h    = (const float*)d_in[0];
    const int*   src  = (const int*)d_in[1];
    const int*   dst  = (const int*)d_in[2];
    const float* WQ   = (const float*)d_in[3];
    const float* WK   = (const float*)d_in[4];
    const float* WV   = (const float*)d_in[5];
    const float* WO   = (const float*)d_in[6];
    const float* bO   = (const float*)d_in[7];
    const float* W1   = (const float*)d_in[8];
    const float* b1   = (const float*)d_in[9];
    const float* W2   = (const float*)d_in[10];
    const float* b2   = (const float*)d_in[11];
    const float* bn1g = (const float*)d_in[12];
    const float* bn1b = (const float*)d_in[13];
    const float* bn2g = (const float*)d_in[14];
    const float* bn2b = (const float*)d_in[15];
    float* out = (float*)d_out;

    int M = in_sizes[0] / D;
    int E = in_sizes[1];
    if (M > N_NODES) M = N_NODES;
    if (E > N_EDGES) E = N_EDGES;

    float *Qp, *Kp, *Vp, *wVp, *zp, *x1p, *midp, *x2p, *stp, *bn1p, *bn2p;
    __nv_bfloat16 *whp, *wlp;
    cudaGetSymbolAddress((void**)&Qp,  g_Q);
    cudaGetSymbolAddress((void**)&Kp,  g_Kf);
    cudaGetSymbolAddress((void**)&Vp,  g_Vf);
    cudaGetSymbolAddress((void**)&wVp, g_wV);
    cudaGetSymbolAddress((void**)&zp,  g_z);
    cudaGetSymbolAddress((void**)&x1p, g_x1);
    cudaGetSymbolAddress((void**)&midp, g_mid);
    cudaGetSymbolAddress((void**)&x2p, g_x2);
    cudaGetSymbolAddress((void**)&stp, g_stats);
    cudaGetSymbolAddress((void**)&bn1p, g_bn1);
    cudaGetSymbolAddress((void**)&bn2p, g_bn2);
    cudaGetSymbolAddress((void**)&whp, g_wh);
    cudaGetSymbolAddress((void**)&wlp, g_wl);

    cudaFuncSetAttribute(qkv_kernel, cudaFuncAttributeMaxDynamicSharedMemorySize, DSMEM_BYTES);
    cudaFuncSetAttribute(tgemm_k<ATR_DIVZ, EPI_BIAS_RESID, false, true, 128>,
                         cudaFuncAttributeMaxDynamicSharedMemorySize, DSMEM_BYTES);
    cudaFuncSetAttribute(tgemm_k<ATR_BN, EPI_BIAS_RELU, false, false, 128>,
                         cudaFuncAttributeMaxDynamicSharedMemorySize, DSMEM_BYTES);
    cudaFuncSetAttribute(tgemm_k<ATR_NONE, EPI_BIAS_RESID, true, true, 256>,
                         cudaFuncAttributeMaxDynamicSharedMemorySize, DSMEM_BYTES);

    dim3 blk(256);
    int gx = (M + 127) / 128;

    zero_scratch<<<2048, 256>>>();
    convert_weights<<<W_TOTAL / 2 / 256, 256>>>(WQ, WK, WV, WO, W1, W2);

    // fused QKV projections
    qkv_kernel<<<dim3(gx, 3), blk, DSMEM_BYTES>>>(h, Qp, Kp, Vp, M);

    // edge attention scatter
    edge_kernel<<<(E * H + 255) / 256, 256>>>(Qp, Kp, Vp, src, dst, wVp, zp, E);

    // O projection: (wV/z) @ WO^T + bO + h -> x1  (+ BN1 stats fused)
    tgemm_k<ATR_DIVZ, EPI_BIAS_RESID, false, true, 128><<<dim3(gx, 1), blk, DSMEM_BYTES>>>(
        wVp, whp + OFF_WO, wlp + OFF_WO, bO, h, zp, nullptr, stp, stp + D, x1p, M, D);

    bn_finalize<<<1, D>>>(stp, stp + D, bn1g, bn1b, bn1p, bn1p + D, M);

    // FFN1: relu(BN1(x1) @ W1^T + b1) -> mid [N, 256]
    tgemm_k<ATR_BN, EPI_BIAS_RELU, false, false, 128><<<dim3(gx, 2), blk, DSMEM_BYTES>>>(
        x1p, whp + OFF_W1, wlp + OFF_W1, b1, nullptr, bn1p, bn1p + D, nullptr, nullptr,
        midp, M, 2 * D);

    // FFN2: mid @ W2^T + b2 + BN1(x1) -> x2  (+ BN2 stats fused)
    tgemm_k<ATR_NONE, EPI_BIAS_RESID, true, true, 256><<<dim3(gx, 1), blk, DSMEM_BYTES>>>(
        midp, whp + OFF_W2, wlp + OFF_W2, b2, x1p, bn1p, bn1p + D, stp + 2 * D, stp + 3 * D,
        x2p, M, D);

    bn_finalize<<<1, D>>>(stp + 2 * D, stp + 3 * D, bn2g, bn2b, bn2p, bn2p + D, M);
    bn_apply<<<2048, 256>>>(x2p, bn2p, out, M);
}

// round 6
// speedup vs baseline: 1.6962x; 1.0896x over previous
#include <cuda_runtime.h>
#include <cuda_bf16.h>
#include <math.h>
#include <stdint.h>

#define N_NODES 50000
#define N_EDGES 640000
#define D 128
#define H 8

// ---------------- scratch (static device globals; no allocation) ----------------
__device__ float g_Q [N_NODES * D];
__device__ float g_Kf[N_NODES * D];
__device__ float g_Vf[N_NODES * D];
__device__ float g_attn[N_NODES * D];
__device__ float g_x1[N_NODES * D];
__device__ float g_mid[N_NODES * 2 * D];
__device__ float g_x2[N_NODES * D];
__device__ float g_stats[4 * D];
__device__ float g_bn1[2 * D];
__device__ float g_bn2[2 * D];
// CSR for dst-grouped edges
__device__ int g_rowptr[N_NODES + 1];
__device__ int g_cursor[N_NODES];
__device__ int g_csrc[N_EDGES];
// pre-converted weights: hi and lo bf16, row-major as fp32 source
#define W_TOTAL 131072  // 4*128*128 + 256*128 + 128*256
__device__ __nv_bfloat16 g_wh[W_TOTAL];
__device__ __nv_bfloat16 g_wl[W_TOTAL];
#define OFF_WQ 0
#define OFF_WK 16384
#define OFF_WV 32768
#define OFF_WO 49152
#define OFF_W1 65536
#define OFF_W2 98304

// ---------------- helpers ----------------
__device__ __forceinline__ uint32_t smem_u32(const void* p) {
    uint32_t a;
    asm("{ .reg .u64 t; cvta.to.shared.u64 t, %1; cvt.u32.u64 %0, t; }" : "=r"(a) : "l"(p));
    return a;
}
__device__ __forceinline__ void ldm_x4(uint32_t& a0, uint32_t& a1, uint32_t& a2, uint32_t& a3,
                                       uint32_t addr) {
    asm volatile("ldmatrix.sync.aligned.m8n8.x4.shared.b16 {%0,%1,%2,%3}, [%4];"
                 : "=r"(a0), "=r"(a1), "=r"(a2), "=r"(a3) : "r"(addr));
}
__device__ __forceinline__ void ldm_x2(uint32_t& b0, uint32_t& b1, uint32_t addr) {
    asm volatile("ldmatrix.sync.aligned.m8n8.x2.shared.b16 {%0,%1}, [%2];"
                 : "=r"(b0), "=r"(b1) : "r"(addr));
}
__device__ __forceinline__ void mma_bf16(float* c, uint32_t a0, uint32_t a1, uint32_t a2,
                                         uint32_t a3, uint32_t b0, uint32_t b1) {
    asm volatile(
        "mma.sync.aligned.m16n8k16.row.col.f32.bf16.bf16.f32 "
        "{%0,%1,%2,%3}, {%4,%5,%6,%7}, {%8,%9}, {%0,%1,%2,%3};"
        : "+f"(c[0]), "+f"(c[1]), "+f"(c[2]), "+f"(c[3])
        : "r"(a0), "r"(a1), "r"(a2), "r"(a3), "r"(b0), "r"(b1));
}
__device__ __forceinline__ uint32_t split_pair(float a, float b, uint32_t& lo) {
    uint32_t h;
    asm("cvt.rn.bf16x2.f32 %0, %1, %2;" : "=r"(h) : "f"(b), "f"(a));
    float ra = a - __uint_as_float(h << 16);
    float rb = b - __uint_as_float(h & 0xffff0000u);
    asm("cvt.rn.bf16x2.f32 %0, %1, %2;" : "=r"(lo) : "f"(rb), "f"(ra));
    return h;
}
__device__ __forceinline__ void cp16(uint32_t dst, const void* src) {
    asm volatile("cp.async.cg.shared.global [%0], [%1], 16;" :: "r"(dst), "l"(src));
}
#define CP_COMMIT() asm volatile("cp.async.commit_group;" ::: "memory")
#define CP_WAIT0()  asm volatile("cp.async.wait_group 0;" ::: "memory")

// ---------------- weight conversion ----------------
__global__ void convert_weights(const float* __restrict__ WQ, const float* __restrict__ WK,
                                const float* __restrict__ WV, const float* __restrict__ WO,
                                const float* __restrict__ W1, const float* __restrict__ W2)
{
    int p = blockIdx.x * blockDim.x + threadIdx.x;
    if (p >= W_TOTAL / 2) return;
    int elem = p * 2;
    const float* src;
    int local;
    if (elem < OFF_W1) {
        int m = elem >> 14;
        local = elem & 16383;
        src = (m == 0) ? WQ : (m == 1) ? WK : (m == 2) ? WV : WO;
    } else if (elem < OFF_W2) {
        local = elem - OFF_W1;
        src = W1;
    } else {
        local = elem - OFF_W2;
        src = W2;
    }
    float a = src[local], b = src[local + 1];
    uint32_t lo;
    uint32_t hi = split_pair(a, b, lo);
    ((uint32_t*)g_wh)[p] = hi;
    ((uint32_t*)g_wl)[p] = lo;
}

// ---------------- zero (histogram + stats) ----------------
__global__ void zero_scratch() {
    int tid = blockIdx.x * blockDim.x + threadIdx.x;
    int stride = gridDim.x * blockDim.x;
    for (int i = tid; i < N_NODES; i += stride) g_cursor[i] = 0;
    if (tid < 4 * D) g_stats[tid] = 0.f;
}

// ---------------- CSR build ----------------
__global__ void hist_kernel(const int* __restrict__ dst, int E) {
    int e = blockIdx.x * blockDim.x + threadIdx.x;
    if (e < E) atomicAdd(&g_cursor[dst[e]], 1);
}

#define SCAN_T 1024
#define BPT ((N_NODES + SCAN_T - 1) / SCAN_T)   // 49
__global__ __launch_bounds__(SCAN_T) void scan_kernel(int n, int E) {
    int tid = threadIdx.x;
    int base = tid * BPT;
    int cnt[BPT];
    int s = 0;
#pragma unroll
    for (int i = 0; i < BPT; ++i) {
        int idx = base + i;
        int c = (idx < n) ? g_cursor[idx] : 0;
        cnt[i] = c;
        s += c;
    }
    __shared__ int ts[SCAN_T];
    ts[tid] = s;
    __syncthreads();
    for (int off = 1; off < SCAN_T; off <<= 1) {
        int v = (tid >= off) ? ts[tid - off] : 0;
        __syncthreads();
        ts[tid] += v;
        __syncthreads();
    }
    int run = ts[tid] - s;
#pragma unroll
    for (int i = 0; i < BPT; ++i) {
        int idx = base + i;
        if (idx < n) {
            g_rowptr[idx] = run;
            g_cursor[idx] = run;
            run += cnt[i];
        }
    }
    if (tid == SCAN_T - 1) g_rowptr[n] = E;
}

__global__ void scatter_kernel(const int* __restrict__ src, const int* __restrict__ dst, int E) {
    int e = blockIdx.x * blockDim.x + threadIdx.x;
    if (e < E) {
        int pos = atomicAdd(&g_cursor[dst[e]], 1);
        g_csrc[pos] = src[e];
    }
}

// ---------------- gather attention: warp per destination node ----------------
__global__ __launch_bounds__(256) void gather_kernel(
    const float* __restrict__ Q, const float* __restrict__ K, const float* __restrict__ V,
    float* __restrict__ attn, int n)
{
    int warp = (blockIdx.x * blockDim.x + threadIdx.x) >> 5;
    if (warp >= n) return;
    const int lid = threadIdx.x & 31;
    const int d = warp;

    float4 q = *(const float4*)(Q + (size_t)d * D + lid * 4);
    float4 acc = make_float4(0.f, 0.f, 0.f, 0.f);
    float zacc = 0.f;

    int beg = g_rowptr[d], end = g_rowptr[d + 1];
    int i = beg;
    for (; i + 2 <= end; i += 2) {
        int s0 = g_csrc[i], s1 = g_csrc[i + 1];
        float4 k0 = *(const float4*)(K + (size_t)s0 * D + lid * 4);
        float4 k1 = *(const float4*)(K + (size_t)s1 * D + lid * 4);
        float4 v0 = *(const float4*)(V + (size_t)s0 * D + lid * 4);
        float4 v1 = *(const float4*)(V + (size_t)s1 * D + lid * 4);
        float p0 = q.x * k0.x + q.y * k0.y + q.z * k0.z + q.w * k0.w;
        float p1 = q.x * k1.x + q.y * k1.y + q.z * k1.z + q.w * k1.w;
        p0 += __shfl_xor_sync(0xffffffffu, p0, 1);
        p1 += __shfl_xor_sync(0xffffffffu, p1, 1);
        p0 += __shfl_xor_sync(0xffffffffu, p0, 2);
        p1 += __shfl_xor_sync(0xffffffffu, p1, 2);
        float sc0 = __expf(fminf(fmaxf(p0 * 0.25f, -5.f), 5.f));
        float sc1 = __expf(fminf(fmaxf(p1 * 0.25f, -5.f), 5.f));
        acc.x += v0.x * sc0 + v1.x * sc1;
        acc.y += v0.y * sc0 + v1.y * sc1;
        acc.z += v0.z * sc0 + v1.z * sc1;
        acc.w += v0.w * sc0 + v1.w * sc1;
        zacc += sc0 + sc1;
    }
    if (i < end) {
        int s0 = g_csrc[i];
        float4 k0 = *(const float4*)(K + (size_t)s0 * D + lid * 4);
        float4 v0 = *(const float4*)(V + (size_t)s0 * D + lid * 4);
        float p0 = q.x * k0.x + q.y * k0.y + q.z * k0.z + q.w * k0.w;
        p0 += __shfl_xor_sync(0xffffffffu, p0, 1);
        p0 += __shfl_xor_sync(0xffffffffu, p0, 2);
        float sc0 = __expf(fminf(fmaxf(p0 * 0.25f, -5.f), 5.f));
        acc.x += v0.x * sc0; acc.y += v0.y * sc0;
        acc.z += v0.z * sc0; acc.w += v0.w * sc0;
        zacc += sc0;
    }
    float inv = 1.0f / zacc;
    acc.x *= inv; acc.y *= inv; acc.z *= inv; acc.w *= inv;
    *(float4*)(attn + (size_t)d * D + lid * 4) = acc;
}

// ---------------- tensor-core GEMM ----------------
enum { ATR_NONE = 0, ATR_BN = 2 };
enum { EPI_STORE = 0, EPI_BIAS_RESID = 1, EPI_BIAS_RELU = 2 };

#define SK 72
#define TILE_BYTES (128 * SK * 2)
#define DSMEM_BYTES (4 * TILE_BYTES)

template <int ATR, int EPI, bool RESBN, bool STATS, int KT>
__device__ __forceinline__ void tgemm_core(
    const float* __restrict__ A,
    const __nv_bfloat16* __restrict__ Wh, const __nv_bfloat16* __restrict__ Wl,
    const float* __restrict__ bias, const float* __restrict__ resid,
    const float* __restrict__ t0, const float* __restrict__ t1,
    float* __restrict__ ssum, float* __restrict__ ssq,
    float* __restrict__ C, int M, int ldc, int rowBase, int colBase)
{
    extern __shared__ __align__(16) char sm[];
    char* sAhi = sm;
    char* sAlo = sm + TILE_BYTES;
    char* sWhi = sm + 2 * TILE_BYTES;
    char* sWlo = sm + 3 * TILE_BYTES;

    const int tid = threadIdx.x;
    const int wid = tid >> 5;
    const int lid = tid & 31;
    const int warp_m = wid & 1;
    const int warp_n = wid >> 1;

    const int ar = (lid & 7) + ((lid >> 3) & 1) * 8;
    const int ac = (lid >> 4) * 8;
    const int br = lid & 7;
    const int bc = ((lid >> 3) & 1) * 8;

    const uint32_t saHi = smem_u32(sAhi), saLo = smem_u32(sAlo);
    const uint32_t swHi = smem_u32(sWhi), swLo = smem_u32(sWlo);
    const uint32_t aOff = (uint32_t)((warp_m * 64 + ar) * SK + ac) * 2;
    const uint32_t bOff = (uint32_t)((warp_n * 32 + br) * SK + bc) * 2;

    float acc[4][4][4];
#pragma unroll
    for (int i = 0; i < 4; ++i)
#pragma unroll
        for (int j = 0; j < 4; ++j)
#pragma unroll
            for (int t = 0; t < 4; ++t) acc[i][j][t] = 0.f;

    const int row = tid >> 1;
    const int kh = (tid & 1) * 32;
    const int grow = rowBase + row;
    const bool valid = grow < M;

    constexpr int NSLAB = KT / 64;
#pragma unroll
    for (int slab = 0; slab < NSLAB; ++slab) {
        const int slabK = slab * 64;

        {
            const __nv_bfloat16* Whp = Wh + (size_t)(colBase + row) * KT + slabK + kh;
            const __nv_bfloat16* Wlp = Wl + (size_t)(colBase + row) * KT + slabK + kh;
            uint32_t dh = swHi + (uint32_t)(row * SK + kh) * 2;
            uint32_t dl = swLo + (uint32_t)(row * SK + kh) * 2;
#pragma unroll
            for (int c = 0; c < 4; ++c) cp16(dh + c * 16, Whp + c * 8);
#pragma unroll
            for (int c = 0; c < 4; ++c) cp16(dl + c * 16, Wlp + c * 8);
            CP_COMMIT();
        }

        {
            const float* Ar = A + (size_t)grow * KT + slabK + kh;
#pragma unroll
            for (int g = 0; g < 4; ++g) {
                float4 f0 = make_float4(0.f, 0.f, 0.f, 0.f), f1 = f0;
                if (valid) {
                    f0 = *(const float4*)(Ar + g * 8);
                    f1 = *(const float4*)(Ar + g * 8 + 4);
                    int kg = slabK + kh + g * 8;
                    if (ATR == ATR_BN) {
                        float4 sc0 = *(const float4*)(t0 + kg);
                        float4 sc1 = *(const float4*)(t0 + kg + 4);
                        float4 sh0 = *(const float4*)(t1 + kg);
                        float4 sh1 = *(const float4*)(t1 + kg + 4);
                        f0.x = f0.x * sc0.x + sh0.x; f0.y = f0.y * sc0.y + sh0.y;
                        f0.z = f0.z * sc0.z + sh0.z; f0.w = f0.w * sc0.w + sh0.w;
                        f1.x = f1.x * sc1.x + sh1.x; f1.y = f1.y * sc1.y + sh1.y;
                        f1.z = f1.z * sc1.z + sh1.z; f1.w = f1.w * sc1.w + sh1.w;
                    }
                }
                uint4 hi, lo;
                hi.x = split_pair(f0.x, f0.y, lo.x);
                hi.y = split_pair(f0.z, f0.w, lo.y);
                hi.z = split_pair(f1.x, f1.y, lo.z);
                hi.w = split_pair(f1.z, f1.w, lo.w);
                uint32_t off = (uint32_t)(row * SK + kh + g * 8) * 2;
                *(uint4*)(sAhi + off) = hi;
                *(uint4*)(sAlo + off) = lo;
            }
        }
        CP_WAIT0();
        __syncthreads();

#pragma unroll
        for (int ks = 0; ks < 4; ++ks) {
            const uint32_t k0 = (uint32_t)(ks * 16) * 2;
            uint32_t bh[4][2], bl[4][2];
#pragma unroll
            for (int j = 0; j < 4; ++j) {
                uint32_t boff = bOff + (uint32_t)(j * 8 * SK) * 2 + k0;
                ldm_x2(bh[j][0], bh[j][1], swHi + boff);
                ldm_x2(bl[j][0], bl[j][1], swLo + boff);
            }
#pragma unroll
            for (int i = 0; i < 4; ++i) {
                uint32_t aoff = aOff + (uint32_t)(i * 16 * SK) * 2 + k0;
                uint32_t ah0, ah1, ah2, ah3, al0, al1, al2, al3;
                ldm_x4(ah0, ah1, ah2, ah3, saHi + aoff);
                ldm_x4(al0, al1, al2, al3, saLo + aoff);
#pragma unroll
                for (int j = 0; j < 4; ++j) {
                    mma_bf16(acc[i][j], ah0, ah1, ah2, ah3, bh[j][0], bh[j][1]);
                    mma_bf16(acc[i][j], ah0, ah1, ah2, ah3, bl[j][0], bl[j][1]);
                    mma_bf16(acc[i][j], al0, al1, al2, al3, bh[j][0], bh[j][1]);
                }
            }
        }
        if (slab + 1 < NSLAB) __syncthreads();
    }

    const int rr = lid >> 2;
    const int cc = (lid & 3) * 2;
    float cs[8], cq[8];
    if (STATS) {
#pragma unroll
        for (int t = 0; t < 8; ++t) { cs[t] = 0.f; cq[t] = 0.f; }
    }
#pragma unroll
    for (int i = 0; i < 4; ++i) {
#pragma unroll
        for (int half = 0; half < 2; ++half) {
            int r = rowBase + warp_m * 64 + i * 16 + rr + half * 8;
            if (r >= M) continue;
            float* Crow = C + (size_t)r * ldc;
            const float* Rrow = resid ? resid + (size_t)r * D : nullptr;
#pragma unroll
            for (int j = 0; j < 4; ++j) {
                int col = colBase + warp_n * 32 + j * 8 + cc;
                float v0 = acc[i][j][half * 2];
                float v1 = acc[i][j][half * 2 + 1];
                if (EPI == EPI_BIAS_RESID) {
                    v0 += bias[col];
                    v1 += bias[col + 1];
                    float r0 = Rrow[col], r1 = Rrow[col + 1];
                    if (RESBN) {
                        r0 = r0 * t0[col] + t1[col];
                        r1 = r1 * t0[col + 1] + t1[col + 1];
                    }
                    v0 += r0; v1 += r1;
                } else if (EPI == EPI_BIAS_RELU) {
                    v0 = fmaxf(v0 + bias[col], 0.f);
                    v1 = fmaxf(v1 + bias[col + 1], 0.f);
                }
                if (STATS) {
                    cs[j * 2] += v0;     cq[j * 2] += v0 * v0;
                    cs[j * 2 + 1] += v1; cq[j * 2 + 1] += v1 * v1;
                }
                *(float2*)(Crow + col) = make_float2(v0, v1);
            }
        }
    }
    if (STATS) {
#pragma unroll
        for (int t = 0; t < 8; ++t) {
#pragma unroll
            for (int o = 4; o < 32; o <<= 1) {
                cs[t] += __shfl_xor_sync(0xffffffffu, cs[t], o);
                cq[t] += __shfl_xor_sync(0xffffffffu, cq[t], o);
            }
        }
        if (lid < 4) {
#pragma unroll
            for (int t = 0; t < 8; ++t) {
                int col = colBase + warp_n * 32 + (t >> 1) * 8 + lid * 2 + (t & 1);
                atomicAdd(&ssum[col & (D - 1)], cs[t]);
                atomicAdd(&ssq[col & (D - 1)], cq[t]);
            }
        }
    }
}

template <int ATR, int EPI, bool RESBN, bool STATS, int KT>
__global__ __launch_bounds__(256, 2) void tgemm_k(
    const float* __restrict__ A,
    const __nv_bfloat16* __restrict__ Wh, const __nv_bfloat16* __restrict__ Wl,
    const float* __restrict__ bias, const float* __restrict__ resid,
    const float* __restrict__ t0, const float* __restrict__ t1,
    float* __restrict__ ssum, float* __restrict__ ssq,
    float* __restrict__ C, int M, int ldc)
{
    tgemm_core<ATR, EPI, RESBN, STATS, KT>(A, Wh, Wl, bias, resid, t0, t1, ssum, ssq,
                                           C, M, ldc, blockIdx.x * 128, blockIdx.y * 128);
}

__global__ __launch_bounds__(256, 2) void qkv_kernel(
    const float* __restrict__ h,
    float* __restrict__ Q, float* __restrict__ K, float* __restrict__ V, int M)
{
    int off = (blockIdx.y == 0) ? OFF_WQ : (blockIdx.y == 1) ? OFF_WK : OFF_WV;
    float* C = (blockIdx.y == 0) ? Q : (blockIdx.y == 1) ? K : V;
    tgemm_core<ATR_NONE, EPI_STORE, false, false, 128>(
        h, g_wh + off, g_wl + off, nullptr, nullptr, nullptr, nullptr, nullptr, nullptr,
        C, M, D, blockIdx.x * 128, 0);
}

// ---------------- batch-norm finalize/apply ----------------
__global__ void bn_finalize(const float* __restrict__ sum, const float* __restrict__ sq,
                            const float* __restrict__ g, const float* __restrict__ b,
                            float* __restrict__ scale, float* __restrict__ shift, int M)
{
    int c = threadIdx.x;
    float invM = 1.0f / (float)M;
    float mu = sum[c] * invM;
    float var = sq[c] * invM - mu * mu;
    float sc = g[c] * rsqrtf(var + 1e-5f);
    scale[c] = sc;
    shift[c] = b[c] - mu * sc;
}

__global__ void bn_apply(const float* __restrict__ x, const float* __restrict__ bn,
                         float* __restrict__ out, int M)
{
    int tid = blockIdx.x * blockDim.x + threadIdx.x;
    int stride = gridDim.x * blockDim.x;
    int total = M * D;
    for (int i = tid; i < total; i += stride) {
        int c = i & (D - 1);
        out[i] = x[i] * bn[c] + bn[D + c];
    }
}

// ---------------- host launch ----------------
extern "C" void kernel_launch(void* const* d_in, const int* in_sizes, int n_in,
                              void* d_out, int out_size)
{
    const float* h    = (const float*)d_in[0];
    const int*   src  = (const int*)d_in[1];
    const int*   dst  = (const int*)d_in[2];
    const float* WQ   = (const float*)d_in[3];
    const float* WK   = (const float*)d_in[4];
    const float* WV   = (const float*)d_in[5];
    const float* WO   = (const float*)d_in[6];
    const float* bO   = (const float*)d_in[7];
    const float* W1   = (const float*)d_in[8];
    const float* b1   = (const float*)d_in[9];
    const float* W2   = (const float*)d_in[10];
    const float* b2   = (const float*)d_in[11];
    const float* bn1g = (const float*)d_in[12];
    const float* bn1b = (const float*)d_in[13];
    const float* bn2g = (const float*)d_in[14];
    const float* bn2b = (const float*)d_in[15];
    float* out = (float*)d_out;

    int M = in_sizes[0] / D;
    int E = in_sizes[1];
    if (M > N_NODES) M = N_NODES;
    if (E > N_EDGES) E = N_EDGES;

    float *Qp, *Kp, *Vp, *attnp, *x1p, *midp, *x2p, *stp, *bn1p, *bn2p;
    __nv_bfloat16 *whp, *wlp;
    cudaGetSymbolAddress((void**)&Qp,  g_Q);
    cudaGetSymbolAddress((void**)&Kp,  g_Kf);
    cudaGetSymbolAddress((void**)&Vp,  g_Vf);
    cudaGetSymbolAddress((void**)&attnp, g_attn);
    cudaGetSymbolAddress((void**)&x1p, g_x1);
    cudaGetSymbolAddress((void**)&midp, g_mid);
    cudaGetSymbolAddress((void**)&x2p, g_x2);
    cudaGetSymbolAddress((void**)&stp, g_stats);
    cudaGetSymbolAddress((void**)&bn1p, g_bn1);
    cudaGetSymbolAddress((void**)&bn2p, g_bn2);
    cudaGetSymbolAddress((void**)&whp, g_wh);
    cudaGetSymbolAddress((void**)&wlp, g_wl);

    cudaFuncSetAttribute(qkv_kernel, cudaFuncAttributeMaxDynamicSharedMemorySize, DSMEM_BYTES);
    cudaFuncSetAttribute(tgemm_k<ATR_NONE, EPI_BIAS_RESID, false, true, 128>,
                         cudaFuncAttributeMaxDynamicSharedMemorySize, DSMEM_BYTES);
    cudaFuncSetAttribute(tgemm_k<ATR_BN, EPI_BIAS_RELU, false, false, 128>,
                         cudaFuncAttributeMaxDynamicSharedMemorySize, DSMEM_BYTES);
    cudaFuncSetAttribute(tgemm_k<ATR_NONE, EPI_BIAS_RESID, true, true, 256>,
                         cudaFuncAttributeMaxDynamicSharedMemorySize, DSMEM_BYTES);

    dim3 blk(256);
    int gx = (M + 127) / 128;

    zero_scratch<<<256, 256>>>();
    convert_weights<<<W_TOTAL / 2 / 256, 256>>>(WQ, WK, WV, WO, W1, W2);

    // CSR build (dst-grouped)
    hist_kernel<<<(E + 255) / 256, 256>>>(dst, E);
    scan_kernel<<<1, SCAN_T>>>(M, E);
    scatter_kernel<<<(E + 255) / 256, 256>>>(src, dst, E);

    // fused QKV projections
    qkv_kernel<<<dim3(gx, 3), blk, DSMEM_BYTES>>>(h, Qp, Kp, Vp, M);

    // gather attention (writes normalized attn directly)
    gather_kernel<<<(M * 32 + 255) / 256, 256>>>(Qp, Kp, Vp, attnp, M);

    // O projection: attn @ WO^T + bO + h -> x1  (+ BN1 stats fused)
    tgemm_k<ATR_NONE, EPI_BIAS_RESID, false, true, 128><<<dim3(gx, 1), blk, DSMEM_BYTES>>>(
        attnp, whp + OFF_WO, wlp + OFF_WO, bO, h, nullptr, nullptr, stp, stp + D, x1p, M, D);

    bn_finalize<<<1, D>>>(stp, stp + D, bn1g, bn1b, bn1p, bn1p + D, M);

    // FFN1: relu(BN1(x1) @ W1^T + b1) -> mid [N, 256]
    tgemm_k<ATR_BN, EPI_BIAS_RELU, false, false, 128><<<dim3(gx, 2), blk, DSMEM_BYTES>>>(
        x1p, whp + OFF_W1, wlp + OFF_W1, b1, nullptr, bn1p, bn1p + D, nullptr, nullptr,
        midp, M, 2 * D);

    // FFN2: mid @ W2^T + b2 + BN1(x1) -> x2  (+ BN2 stats fused)
    tgemm_k<ATR_NONE, EPI_BIAS_RESID, true, true, 256><<<dim3(gx, 1), blk, DSMEM_BYTES>>>(
        midp, whp + OFF_W2, wlp + OFF_W2, b2, x1p, bn1p, bn1p + D, stp + 2 * D, stp + 3 * D,
        x2p, M, D);

    bn_finalize<<<1, D>>>(stp + 2 * D, stp + 3 * D, bn2g, bn2b, bn2p, bn2p + D, M);
    bn_apply<<<2048, 256>>>(x2p, bn2p, out, M);
}

// round 7
// speedup vs baseline: 2.0436x; 1.2048x over previous
#include <cuda_runtime.h>
#include <cuda_bf16.h>
#include <math.h>
#include <stdint.h>

#define N_NODES 50000
#define N_EDGES 640000
#define D 128
#define H 8

// ---------------- scratch (static device globals; no allocation) ----------------
__device__ float g_Q [N_NODES * D];
__device__ float g_Kf[N_NODES * D];
__device__ float g_Vf[N_NODES * D];
__device__ float g_attn[N_NODES * D];
__device__ float g_x1[N_NODES * D];
__device__ float g_mid[N_NODES * 2 * D];
__device__ float g_x2[N_NODES * D];
__device__ float g_stats[4 * D];
__device__ float g_bn1[2 * D];
__device__ float g_bn2[2 * D];
// CSR for dst-grouped edges
__device__ int g_rowptr[N_NODES + 1];
__device__ int g_cursor[N_NODES];
__device__ int g_csrc[N_EDGES];
#define SCAN_BLOCKS ((N_NODES + 255) / 256)   // 196
__device__ int g_part[256];
// pre-converted weights: hi and lo bf16, row-major as fp32 source
#define W_TOTAL 131072  // 4*128*128 + 256*128 + 128*256
__device__ __nv_bfloat16 g_wh[W_TOTAL];
__device__ __nv_bfloat16 g_wl[W_TOTAL];
#define OFF_WQ 0
#define OFF_WK 16384
#define OFF_WV 32768
#define OFF_WO 49152
#define OFF_W1 65536
#define OFF_W2 98304

// ---------------- helpers ----------------
__device__ __forceinline__ uint32_t smem_u32(const void* p) {
    uint32_t a;
    asm("{ .reg .u64 t; cvta.to.shared.u64 t, %1; cvt.u32.u64 %0, t; }" : "=r"(a) : "l"(p));
    return a;
}
__device__ __forceinline__ void ldm_x4(uint32_t& a0, uint32_t& a1, uint32_t& a2, uint32_t& a3,
                                       uint32_t addr) {
    asm volatile("ldmatrix.sync.aligned.m8n8.x4.shared.b16 {%0,%1,%2,%3}, [%4];"
                 : "=r"(a0), "=r"(a1), "=r"(a2), "=r"(a3) : "r"(addr));
}
__device__ __forceinline__ void ldm_x2(uint32_t& b0, uint32_t& b1, uint32_t addr) {
    asm volatile("ldmatrix.sync.aligned.m8n8.x2.shared.b16 {%0,%1}, [%2];"
                 : "=r"(b0), "=r"(b1) : "r"(addr));
}
__device__ __forceinline__ void mma_bf16(float* c, uint32_t a0, uint32_t a1, uint32_t a2,
                                         uint32_t a3, uint32_t b0, uint32_t b1) {
    asm volatile(
        "mma.sync.aligned.m16n8k16.row.col.f32.bf16.bf16.f32 "
        "{%0,%1,%2,%3}, {%4,%5,%6,%7}, {%8,%9}, {%0,%1,%2,%3};"
        : "+f"(c[0]), "+f"(c[1]), "+f"(c[2]), "+f"(c[3])
        : "r"(a0), "r"(a1), "r"(a2), "r"(a3), "r"(b0), "r"(b1));
}
__device__ __forceinline__ uint32_t split_pair(float a, float b, uint32_t& lo) {
    uint32_t h;
    asm("cvt.rn.bf16x2.f32 %0, %1, %2;" : "=r"(h) : "f"(b), "f"(a));
    float ra = a - __uint_as_float(h << 16);
    float rb = b - __uint_as_float(h & 0xffff0000u);
    asm("cvt.rn.bf16x2.f32 %0, %1, %2;" : "=r"(lo) : "f"(rb), "f"(ra));
    return h;
}
__device__ __forceinline__ void cp16(uint32_t dst, const void* src) {
    asm volatile("cp.async.cg.shared.global [%0], [%1], 16;" :: "r"(dst), "l"(src));
}
#define CP_COMMIT() asm volatile("cp.async.commit_group;" ::: "memory")
#define CP_WAIT0()  asm volatile("cp.async.wait_group 0;" ::: "memory")

// ---------------- weight conversion ----------------
__global__ void convert_weights(const float* __restrict__ WQ, const float* __restrict__ WK,
                                const float* __restrict__ WV, const float* __restrict__ WO,
                                const float* __restrict__ W1, const float* __restrict__ W2)
{
    int p = blockIdx.x * blockDim.x + threadIdx.x;
    if (p >= W_TOTAL / 2) return;
    int elem = p * 2;
    const float* src;
    int local;
    if (elem < OFF_W1) {
        int m = elem >> 14;
        local = elem & 16383;
        src = (m == 0) ? WQ : (m == 1) ? WK : (m == 2) ? WV : WO;
    } else if (elem < OFF_W2) {
        local = elem - OFF_W1;
        src = W1;
    } else {
        local = elem - OFF_W2;
        src = W2;
    }
    float a = src[local], b = src[local + 1];
    uint32_t lo;
    uint32_t hi = split_pair(a, b, lo);
    ((uint32_t*)g_wh)[p] = hi;
    ((uint32_t*)g_wl)[p] = lo;
}

// ---------------- zero (histogram + stats) ----------------
__global__ void zero_scratch() {
    int tid = blockIdx.x * blockDim.x + threadIdx.x;
    int stride = gridDim.x * blockDim.x;
    for (int i = tid; i < N_NODES; i += stride) g_cursor[i] = 0;
    if (tid < 4 * D) g_stats[tid] = 0.f;
}

// ---------------- CSR build ----------------
__global__ void hist_kernel(const int* __restrict__ dst, int E) {
    int e = blockIdx.x * blockDim.x + threadIdx.x;
    if (e < E) atomicAdd(&g_cursor[dst[e]], 1);
}

// phase 1: per-block scan of counts -> local exclusive prefix + block total
__global__ __launch_bounds__(256) void scan_local(int n) {
    int tid = threadIdx.x;
    int lane = tid & 31;
    int wid = tid >> 5;
    int i = blockIdx.x * 256 + tid;
    int c = (i < n) ? g_cursor[i] : 0;
    int v = c;
#pragma unroll
    for (int o = 1; o < 32; o <<= 1) {
        int t = __shfl_up_sync(0xffffffffu, v, o);
        if (lane >= o) v += t;
    }
    __shared__ int wsum[8];
    if (lane == 31) wsum[wid] = v;
    __syncthreads();
    if (wid == 0 && lane < 8) {
        int w = wsum[lane];
#pragma unroll
        for (int o = 1; o < 8; o <<= 1) {
            int t = __shfl_up_sync(0xffu, w, o);
            if (lane >= o) w += t;
        }
        wsum[lane] = w;
    }
    __syncthreads();
    int off = (wid > 0) ? wsum[wid - 1] : 0;
    if (i < n) g_rowptr[i] = v - c + off;   // local exclusive prefix
    if (tid == 255) g_part[blockIdx.x] = v + off;   // block total
}

// phase 2: scan the block totals (<=256)
__global__ __launch_bounds__(256) void scan_part(int nb) {
    int tid = threadIdx.x;
    int lane = tid & 31;
    int wid = tid >> 5;
    int p = (tid < nb) ? g_part[tid] : 0;
    int v = p;
#pragma unroll
    for (int o = 1; o < 32; o <<= 1) {
        int t = __shfl_up_sync(0xffffffffu, v, o);
        if (lane >= o) v += t;
    }
    __shared__ int wsum[8];
    if (lane == 31) wsum[wid] = v;
    __syncthreads();
    if (wid == 0 && lane < 8) {
        int w = wsum[lane];
#pragma unroll
        for (int o = 1; o < 8; o <<= 1) {
            int t = __shfl_up_sync(0xffu, w, o);
            if (lane >= o) w += t;
        }
        wsum[lane] = w;
    }
    __syncthreads();
    int off = (wid > 0) ? wsum[wid - 1] : 0;
    g_part[tid] = v - p + off;   // exclusive
}

// phase 3: add block offsets, init cursor, terminate rowptr
__global__ __launch_bounds__(256) void scan_final(int n, int E) {
    int i = blockIdx.x * 256 + threadIdx.x;
    if (i < n) {
        int r = g_rowptr[i] + g_part[blockIdx.x];
        g_rowptr[i] = r;
        g_cursor[i] = r;
    }
    if (i == 0) g_rowptr[n] = E;
}

__global__ void scatter_kernel(const int* __restrict__ src, const int* __restrict__ dst, int E) {
    int e = blockIdx.x * blockDim.x + threadIdx.x;
    if (e < E) {
        int pos = atomicAdd(&g_cursor[dst[e]], 1);
        g_csrc[pos] = src[e];
    }
}

// ---------------- gather attention: warp per destination node ----------------
__global__ __launch_bounds__(256) void gather_kernel(
    const float* __restrict__ Q, const float* __restrict__ K, const float* __restrict__ V,
    float* __restrict__ attn, int n)
{
    int warp = (blockIdx.x * blockDim.x + threadIdx.x) >> 5;
    if (warp >= n) return;
    const int lid = threadIdx.x & 31;
    const int d = warp;

    float4 q = *(const float4*)(Q + (size_t)d * D + lid * 4);
    float4 acc = make_float4(0.f, 0.f, 0.f, 0.f);
    float zacc = 0.f;

    int beg = g_rowptr[d], end = g_rowptr[d + 1];
    int i = beg;
    for (; i + 2 <= end; i += 2) {
        int s0 = g_csrc[i], s1 = g_csrc[i + 1];
        float4 k0 = *(const float4*)(K + (size_t)s0 * D + lid * 4);
        float4 k1 = *(const float4*)(K + (size_t)s1 * D + lid * 4);
        float4 v0 = *(const float4*)(V + (size_t)s0 * D + lid * 4);
        float4 v1 = *(const float4*)(V + (size_t)s1 * D + lid * 4);
        float p0 = q.x * k0.x + q.y * k0.y + q.z * k0.z + q.w * k0.w;
        float p1 = q.x * k1.x + q.y * k1.y + q.z * k1.z + q.w * k1.w;
        p0 += __shfl_xor_sync(0xffffffffu, p0, 1);
        p1 += __shfl_xor_sync(0xffffffffu, p1, 1);
        p0 += __shfl_xor_sync(0xffffffffu, p0, 2);
        p1 += __shfl_xor_sync(0xffffffffu, p1, 2);
        float sc0 = __expf(fminf(fmaxf(p0 * 0.25f, -5.f), 5.f));
        float sc1 = __expf(fminf(fmaxf(p1 * 0.25f, -5.f), 5.f));
        acc.x += v0.x * sc0 + v1.x * sc1;
        acc.y += v0.y * sc0 + v1.y * sc1;
        acc.z += v0.z * sc0 + v1.z * sc1;
        acc.w += v0.w * sc0 + v1.w * sc1;
        zacc += sc0 + sc1;
    }
    if (i < end) {
        int s0 = g_csrc[i];
        float4 k0 = *(const float4*)(K + (size_t)s0 * D + lid * 4);
        float4 v0 = *(const float4*)(V + (size_t)s0 * D + lid * 4);
        float p0 = q.x * k0.x + q.y * k0.y + q.z * k0.z + q.w * k0.w;
        p0 += __shfl_xor_sync(0xffffffffu, p0, 1);
        p0 += __shfl_xor_sync(0xffffffffu, p0, 2);
        float sc0 = __expf(fminf(fmaxf(p0 * 0.25f, -5.f), 5.f));
        acc.x += v0.x * sc0; acc.y += v0.y * sc0;
        acc.z += v0.z * sc0; acc.w += v0.w * sc0;
        zacc += sc0;
    }
    float inv = 1.0f / zacc;
    acc.x *= inv; acc.y *= inv; acc.z *= inv; acc.w *= inv;
    *(float4*)(attn + (size_t)d * D + lid * 4) = acc;
}

// ---------------- tensor-core GEMM ----------------
enum { ATR_NONE = 0, ATR_BN = 2 };
enum { EPI_STORE = 0, EPI_BIAS_RESID = 1, EPI_BIAS_RELU = 2 };

#define SK 72
#define TILE_BYTES (128 * SK * 2)
#define DSMEM_BYTES (4 * TILE_BYTES)

template <int ATR, int EPI, bool RESBN, bool STATS, int KT>
__device__ __forceinline__ void tgemm_core(
    const float* __restrict__ A,
    const __nv_bfloat16* __restrict__ Wh, const __nv_bfloat16* __restrict__ Wl,
    const float* __restrict__ bias, const float* __restrict__ resid,
    const float* __restrict__ t0, const float* __restrict__ t1,
    float* __restrict__ ssum, float* __restrict__ ssq,
    float* __restrict__ C, int M, int ldc, int rowBase, int colBase)
{
    extern __shared__ __align__(16) char sm[];
    char* sAhi = sm;
    char* sAlo = sm + TILE_BYTES;
    char* sWhi = sm + 2 * TILE_BYTES;
    char* sWlo = sm + 3 * TILE_BYTES;

    const int tid = threadIdx.x;
    const int wid = tid >> 5;
    const int lid = tid & 31;
    const int warp_m = wid & 1;
    const int warp_n = wid >> 1;

    const int ar = (lid & 7) + ((lid >> 3) & 1) * 8;
    const int ac = (lid >> 4) * 8;
    const int br = lid & 7;
    const int bc = ((lid >> 3) & 1) * 8;

    const uint32_t saHi = smem_u32(sAhi), saLo = smem_u32(sAlo);
    const uint32_t swHi = smem_u32(sWhi), swLo = smem_u32(sWlo);
    const uint32_t aOff = (uint32_t)((warp_m * 64 + ar) * SK + ac) * 2;
    const uint32_t bOff = (uint32_t)((warp_n * 32 + br) * SK + bc) * 2;

    float acc[4][4][4];
#pragma unroll
    for (int i = 0; i < 4; ++i)
#pragma unroll
        for (int j = 0; j < 4; ++j)
#pragma unroll
            for (int t = 0; t < 4; ++t) acc[i][j][t] = 0.f;

    const int row = tid >> 1;
    const int kh = (tid & 1) * 32;
    const int grow = rowBase + row;
    const bool valid = grow < M;

    constexpr int NSLAB = KT / 64;
#pragma unroll
    for (int slab = 0; slab < NSLAB; ++slab) {
        const int slabK = slab * 64;

        {
            const __nv_bfloat16* Whp = Wh + (size_t)(colBase + row) * KT + slabK + kh;
            const __nv_bfloat16* Wlp = Wl + (size_t)(colBase + row) * KT + slabK + kh;
            uint32_t dh = swHi + (uint32_t)(row * SK + kh) * 2;
            uint32_t dl = swLo + (uint32_t)(row * SK + kh) * 2;
#pragma unroll
            for (int c = 0; c < 4; ++c) cp16(dh + c * 16, Whp + c * 8);
#pragma unroll
            for (int c = 0; c < 4; ++c) cp16(dl + c * 16, Wlp + c * 8);
            CP_COMMIT();
        }

        {
            const float* Ar = A + (size_t)grow * KT + slabK + kh;
#pragma unroll
            for (int g = 0; g < 4; ++g) {
                float4 f0 = make_float4(0.f, 0.f, 0.f, 0.f), f1 = f0;
                if (valid) {
                    f0 = *(const float4*)(Ar + g * 8);
                    f1 = *(const float4*)(Ar + g * 8 + 4);
                    int kg = slabK + kh + g * 8;
                    if (ATR == ATR_BN) {
                        float4 sc0 = *(const float4*)(t0 + kg);
                        float4 sc1 = *(const float4*)(t0 + kg + 4);
                        float4 sh0 = *(const float4*)(t1 + kg);
                        float4 sh1 = *(const float4*)(t1 + kg + 4);
                        f0.x = f0.x * sc0.x + sh0.x; f0.y = f0.y * sc0.y + sh0.y;
                        f0.z = f0.z * sc0.z + sh0.z; f0.w = f0.w * sc0.w + sh0.w;
                        f1.x = f1.x * sc1.x + sh1.x; f1.y = f1.y * sc1.y + sh1.y;
                        f1.z = f1.z * sc1.z + sh1.z; f1.w = f1.w * sc1.w + sh1.w;
                    }
                }
                uint4 hi, lo;
                hi.x = split_pair(f0.x, f0.y, lo.x);
                hi.y = split_pair(f0.z, f0.w, lo.y);
                hi.z = split_pair(f1.x, f1.y, lo.z);
                hi.w = split_pair(f1.z, f1.w, lo.w);
                uint32_t off = (uint32_t)(row * SK + kh + g * 8) * 2;
                *(uint4*)(sAhi + off) = hi;
                *(uint4*)(sAlo + off) = lo;
            }
        }
        CP_WAIT0();
        __syncthreads();

#pragma unroll
        for (int ks = 0; ks < 4; ++ks) {
            const uint32_t k0 = (uint32_t)(ks * 16) * 2;
            uint32_t bh[4][2], bl[4][2];
#pragma unroll
            for (int j = 0; j < 4; ++j) {
                uint32_t boff = bOff + (uint32_t)(j * 8 * SK) * 2 + k0;
                ldm_x2(bh[j][0], bh[j][1], swHi + boff);
                ldm_x2(bl[j][0], bl[j][1], swLo + boff);
            }
#pragma unroll
            for (int i = 0; i < 4; ++i) {
                uint32_t aoff = aOff + (uint32_t)(i * 16 * SK) * 2 + k0;
                uint32_t ah0, ah1, ah2, ah3, al0, al1, al2, al3;
                ldm_x4(ah0, ah1, ah2, ah3, saHi + aoff);
                ldm_x4(al0, al1, al2, al3, saLo + aoff);
#pragma unroll
                for (int j = 0; j < 4; ++j) {
                    mma_bf16(acc[i][j], ah0, ah1, ah2, ah3, bh[j][0], bh[j][1]);
                    mma_bf16(acc[i][j], ah0, ah1, ah2, ah3, bl[j][0], bl[j][1]);
                    mma_bf16(acc[i][j], al0, al1, al2, al3, bh[j][0], bh[j][1]);
                }
            }
        }
        if (slab + 1 < NSLAB) __syncthreads();
    }

    const int rr = lid >> 2;
    const int cc = (lid & 3) * 2;
    float cs[8], cq[8];
    if (STATS) {
#pragma unroll
        for (int t = 0; t < 8; ++t) { cs[t] = 0.f; cq[t] = 0.f; }
    }
#pragma unroll
    for (int i = 0; i < 4; ++i) {
#pragma unroll
        for (int half = 0; half < 2; ++half) {
            int r = rowBase + warp_m * 64 + i * 16 + rr + half * 8;
            if (r >= M) continue;
            float* Crow = C + (size_t)r * ldc;
            const float* Rrow = resid ? resid + (size_t)r * D : nullptr;
#pragma unroll
            for (int j = 0; j < 4; ++j) {
                int col = colBase + warp_n * 32 + j * 8 + cc;
                float v0 = acc[i][j][half * 2];
                float v1 = acc[i][j][half * 2 + 1];
                if (EPI == EPI_BIAS_RESID) {
                    v0 += bias[col];
                    v1 += bias[col + 1];
                    float r0 = Rrow[col], r1 = Rrow[col + 1];
                    if (RESBN) {
                        r0 = r0 * t0[col] + t1[col];
                        r1 = r1 * t0[col + 1] + t1[col + 1];
                    }
                    v0 += r0; v1 += r1;
                } else if (EPI == EPI_BIAS_RELU) {
                    v0 = fmaxf(v0 + bias[col], 0.f);
                    v1 = fmaxf(v1 + bias[col + 1], 0.f);
                }
                if (STATS) {
                    cs[j * 2] += v0;     cq[j * 2] += v0 * v0;
                    cs[j * 2 + 1] += v1; cq[j * 2 + 1] += v1 * v1;
                }
                *(float2*)(Crow + col) = make_float2(v0, v1);
            }
        }
    }
    if (STATS) {
#pragma unroll
        for (int t = 0; t < 8; ++t) {
#pragma unroll
            for (int o = 4; o < 32; o <<= 1) {
                cs[t] += __shfl_xor_sync(0xffffffffu, cs[t], o);
                cq[t] += __shfl_xor_sync(0xffffffffu, cq[t], o);
            }
        }
        if (lid < 4) {
#pragma unroll
            for (int t = 0; t < 8; ++t) {
                int col = colBase + warp_n * 32 + (t >> 1) * 8 + lid * 2 + (t & 1);
                atomicAdd(&ssum[col & (D - 1)], cs[t]);
                atomicAdd(&ssq[col & (D - 1)], cq[t]);
            }
        }
    }
}

template <int ATR, int EPI, bool RESBN, bool STATS, int KT>
__global__ __launch_bounds__(256, 2) void tgemm_k(
    const float* __restrict__ A,
    const __nv_bfloat16* __restrict__ Wh, const __nv_bfloat16* __restrict__ Wl,
    const float* __restrict__ bias, const float* __restrict__ resid,
    const float* __restrict__ t0, const float* __restrict__ t1,
    float* __restrict__ ssum, float* __restrict__ ssq,
    float* __restrict__ C, int M, int ldc)
{
    tgemm_core<ATR, EPI, RESBN, STATS, KT>(A, Wh, Wl, bias, resid, t0, t1, ssum, ssq,
                                           C, M, ldc, blockIdx.x * 128, blockIdx.y * 128);
}

__global__ __launch_bounds__(256, 2) void qkv_kernel(
    const float* __restrict__ h,
    float* __restrict__ Q, float* __restrict__ K, float* __restrict__ V, int M)
{
    int off = (blockIdx.y == 0) ? OFF_WQ : (blockIdx.y == 1) ? OFF_WK : OFF_WV;
    float* C = (blockIdx.y == 0) ? Q : (blockIdx.y == 1) ? K : V;
    tgemm_core<ATR_NONE, EPI_STORE, false, false, 128>(
        h, g_wh + off, g_wl + off, nullptr, nullptr, nullptr, nullptr, nullptr, nullptr,
        C, M, D, blockIdx.x * 128, 0);
}

// ---------------- batch-norm finalize/apply ----------------
__global__ void bn_finalize(const float* __restrict__ sum, const float* __restrict__ sq,
                            const float* __restrict__ g, const float* __restrict__ b,
                            float* __restrict__ scale, float* __restrict__ shift, int M)
{
    int c = threadIdx.x;
    float invM = 1.0f / (float)M;
    float mu = sum[c] * invM;
    float var = sq[c] * invM - mu * mu;
    float sc = g[c] * rsqrtf(var + 1e-5f);
    scale[c] = sc;
    shift[c] = b[c] - mu * sc;
}

__global__ void bn_apply(const float* __restrict__ x, const float* __restrict__ bn,
                         float* __restrict__ out, int M)
{
    int tid = blockIdx.x * blockDim.x + threadIdx.x;
    int stride = gridDim.x * blockDim.x;
    int total = M * D;
    for (int i = tid; i < total; i += stride) {
        int c = i & (D - 1);
        out[i] = x[i] * bn[c] + bn[D + c];
    }
}

// ---------------- host launch ----------------
extern "C" void kernel_launch(void* const* d_in, const int* in_sizes, int n_in,
                              void* d_out, int out_size)
{
    const float* h    = (const float*)d_in[0];
    const int*   src  = (const int*)d_in[1];
    const int*   dst  = (const int*)d_in[2];
    const float* WQ   = (const float*)d_in[3];
    const float* WK   = (const float*)d_in[4];
    const float* WV   = (const float*)d_in[5];
    const float* WO   = (const float*)d_in[6];
    const float* bO   = (const float*)d_in[7];
    const float* W1   = (const float*)d_in[8];
    const float* b1   = (const float*)d_in[9];
    const float* W2   = (const float*)d_in[10];
    const float* b2   = (const float*)d_in[11];
    const float* bn1g = (const float*)d_in[12];
    const float* bn1b = (const float*)d_in[13];
    const float* bn2g = (const float*)d_in[14];
    const float* bn2b = (const float*)d_in[15];
    float* out = (float*)d_out;

    int M = in_sizes[0] / D;
    int E = in_sizes[1];
    if (M > N_NODES) M = N_NODES;
    if (E > N_EDGES) E = N_EDGES;

    float *Qp, *Kp, *Vp, *attnp, *x1p, *midp, *x2p, *stp, *bn1p, *bn2p;
    __nv_bfloat16 *whp, *wlp;
    cudaGetSymbolAddress((void**)&Qp,  g_Q);
    cudaGetSymbolAddress((void**)&Kp,  g_Kf);
    cudaGetSymbolAddress((void**)&Vp,  g_Vf);
    cudaGetSymbolAddress((void**)&attnp, g_attn);
    cudaGetSymbolAddress((void**)&x1p, g_x1);
    cudaGetSymbolAddress((void**)&midp, g_mid);
    cudaGetSymbolAddress((void**)&x2p, g_x2);
    cudaGetSymbolAddress((void**)&stp, g_stats);
    cudaGetSymbolAddress((void**)&bn1p, g_bn1);
    cudaGetSymbolAddress((void**)&bn2p, g_bn2);
    cudaGetSymbolAddress((void**)&whp, g_wh);
    cudaGetSymbolAddress((void**)&wlp, g_wl);

    cudaFuncSetAttribute(qkv_kernel, cudaFuncAttributeMaxDynamicSharedMemorySize, DSMEM_BYTES);
    cudaFuncSetAttribute(tgemm_k<ATR_NONE, EPI_BIAS_RESID, false, true, 128>,
                         cudaFuncAttributeMaxDynamicSharedMemorySize, DSMEM_BYTES);
    cudaFuncSetAttribute(tgemm_k<ATR_BN, EPI_BIAS_RELU, false, false, 128>,
                         cudaFuncAttributeMaxDynamicSharedMemorySize, DSMEM_BYTES);
    cudaFuncSetAttribute(tgemm_k<ATR_NONE, EPI_BIAS_RESID, true, true, 256>,
                         cudaFuncAttributeMaxDynamicSharedMemorySize, DSMEM_BYTES);

    dim3 blk(256);
    int gx = (M + 127) / 128;
    int nb = (M + 255) / 256;

    zero_scratch<<<256, 256>>>();
    convert_weights<<<W_TOTAL / 2 / 256, 256>>>(WQ, WK, WV, WO, W1, W2);

    // CSR build (dst-grouped) — parallel 3-phase scan
    hist_kernel<<<(E + 255) / 256, 256>>>(dst, E);
    scan_local<<<nb, 256>>>(M);
    scan_part<<<1, 256>>>(nb);
    scan_final<<<nb, 256>>>(M, E);
    scatter_kernel<<<(E + 255) / 256, 256>>>(src, dst, E);

    // fused QKV projections
    qkv_kernel<<<dim3(gx, 3), blk, DSMEM_BYTES>>>(h, Qp, Kp, Vp, M);

    // gather attention (writes normalized attn directly)
    gather_kernel<<<(M * 32 + 255) / 256, 256>>>(Qp, Kp, Vp, attnp, M);

    // O projection: attn @ WO^T + bO + h -> x1  (+ BN1 stats fused)
    tgemm_k<ATR_NONE, EPI_BIAS_RESID, false, true, 128><<<dim3(gx, 1), blk, DSMEM_BYTES>>>(
        attnp, whp + OFF_WO, wlp + OFF_WO, bO, h, nullptr, nullptr, stp, stp + D, x1p, M, D);

    bn_finalize<<<1, D>>>(stp, stp + D, bn1g, bn1b, bn1p, bn1p + D, M);

    // FFN1: relu(BN1(x1) @ W1^T + b1) -> mid [N, 256]
    tgemm_k<ATR_BN, EPI_BIAS_RELU, false, false, 128><<<dim3(gx, 2), blk, DSMEM_BYTES>>>(
        x1p, whp + OFF_W1, wlp + OFF_W1, b1, nullptr, bn1p, bn1p + D, nullptr, nullptr,
        midp, M, 2 * D);

    // FFN2: mid @ W2^T + b2 + BN1(x1) -> x2  (+ BN2 stats fused)
    tgemm_k<ATR_NONE, EPI_BIAS_RESID, true, true, 256><<<dim3(gx, 1), blk, DSMEM_BYTES>>>(
        midp, whp + OFF_W2, wlp + OFF_W2, b2, x1p, bn1p, bn1p + D, stp + 2 * D, stp + 3 * D,
        x2p, M, D);

    bn_finalize<<<1, D>>>(stp + 2 * D, stp + 3 * D, bn2g, bn2b, bn2p, bn2p + D, M);
    bn_apply<<<2048, 256>>>(x2p, bn2p, out, M);
}